// round 13
// baseline (speedup 1.0000x reference)
#include <cuda_runtime.h>
#include <cuda_fp16.h>
#include <math.h>
#include <stdint.h>

#define N_NODES 100000
#define N_EDGES 1600000
#define NGRAPHS 64
#define SCAN_BLK 1024
#define SCAN_NBLK ((N_NODES + SCAN_BLK - 1) / SCAN_BLK)  // 98

// ---------------- device scratch (static globals; no allocation) ----------------
__device__ __align__(16) __half g_tmp [(size_t)N_NODES * 128];
__device__ __align__(16) __half g_bufA[(size_t)N_NODES * 128];
__device__ __align__(16) __half g_bufB[(size_t)N_NODES * 128];
// fp16 weights, transposed to [N][K]: W1@0, W2@16384, W3@32768, W4@49152, W5@57344
__device__ __align__(16) __half g_wh[59392];
__device__ int   g_src[N_EDGES];
__device__ int   g_dst[N_EDGES];
__device__ int   g_batch[N_NODES];
__device__ int   g_is64;
__device__ int   g_deg[N_NODES];
__device__ float g_dinv[N_NODES];
__device__ int   g_off[N_NODES + 1];
__device__ int   g_cur[N_NODES];
__device__ __align__(8) int2 g_edge[N_EDGES];  // (src, __float_as_int(norm))
__device__ int   g_bsum[SCAN_NBLK];
__device__ float g_pool[NGRAPHS * 32];
__device__ int   g_cnt [NGRAPHS];

// ---------------- dtype detection (parallel) + conversion ----------------
__global__ void detect_kernel(const int* __restrict__ w) {
    int i = threadIdx.x;                       // 256 threads
    int v = w[2 * i + 1];
    int any = __syncthreads_or(v != 0);
    if (i == 0) g_is64 = (any == 0);
}

__global__ void init_kernel() {
    int i = blockIdx.x * blockDim.x + threadIdx.x;
    if (i < N_NODES) g_deg[i] = 1;                 // self loop
    if (i < NGRAPHS * 32) g_pool[i] = 0.f;
    if (i < NGRAPHS) g_cnt[i] = 0;
}

// fused: edge dtype convert + degree histogram + batch convert
__global__ void convert_edges(const int* __restrict__ w, const int* __restrict__ bw) {
    int e = blockIdx.x * blockDim.x + threadIdx.x;
    if (e < N_EDGES) {
        int s, d;
        if (g_is64) { s = w[2 * e]; d = w[2 * (N_EDGES + e)]; }
        else        { s = w[e];     d = w[N_EDGES + e]; }
        g_src[e] = s;
        g_dst[e] = d;
        atomicAdd(&g_deg[d], 1);
    }
    if (e < N_NODES) g_batch[e] = g_is64 ? bw[2 * e] : bw[e];
}

// Preconvert all weights to fp16, transposed [N][K]
__global__ void convert_w(const float* __restrict__ W1, const float* __restrict__ W2,
                          const float* __restrict__ W3, const float* __restrict__ W4,
                          const float* __restrict__ W5) {
    int i = blockIdx.x * blockDim.x + threadIdx.x;
    if (i < 16384) {
        int n = i >> 7, k = i & 127;
        g_wh[i] = __float2half(W1[k * 128 + n]);
    } else if (i < 32768) {
        int l = i - 16384; int n = l >> 7, k = l & 127;
        g_wh[i] = __float2half(W2[k * 128 + n]);
    } else if (i < 49152) {
        int l = i - 32768; int n = l >> 7, k = l & 127;
        g_wh[i] = __float2half(W3[k * 128 + n]);
    } else if (i < 57344) {
        int l = i - 49152; int n = l >> 7, k = l & 127;
        g_wh[i] = __float2half(W4[k * 64 + n]);
    } else if (i < 59392) {
        int l = i - 57344; int n = l >> 6, k = l & 63;
        g_wh[i] = __float2half(W5[k * 32 + n]);
    }
}

// Preconvert node features x (fp32) -> fp16 (stored into g_bufB, consumed by layer-1 GEMM)
__global__ void convert_x(const float* __restrict__ x, __half* __restrict__ xh) {
    int i = blockIdx.x * blockDim.x + threadIdx.x;   // one uint4 (8 halves) per thread
    if (i < N_NODES * 128 / 8) {
        float4 f0 = *(const float4*)(x + (size_t)i * 8);
        float4 f1 = *(const float4*)(x + (size_t)i * 8 + 4);
        uint4 u;
        *(__half2*)&u.x = __floats2half2_rn(f0.x, f0.y);
        *(__half2*)&u.y = __floats2half2_rn(f0.z, f0.w);
        *(__half2*)&u.z = __floats2half2_rn(f1.x, f1.y);
        *(__half2*)&u.w = __floats2half2_rn(f1.z, f1.w);
        *(uint4*)(xh + (size_t)i * 8) = u;
    }
}

// ---------------- CSR offsets: block scan (fused dinv) ----------------
__global__ void scan1_kernel() {
    __shared__ int sw[32];
    int tid = threadIdx.x;
    int gi = blockIdx.x * SCAN_BLK + tid;
    int deg = (gi < N_NODES) ? g_deg[gi] : 1;
    if (gi < N_NODES) g_dinv[gi] = rsqrtf((float)deg);
    int val = deg - 1;
    if (gi >= N_NODES) val = 0;
    int v = val;
    int lane = tid & 31, wid = tid >> 5;
#pragma unroll
    for (int o = 1; o < 32; o <<= 1) {
        int n = __shfl_up_sync(0xffffffffu, v, o);
        if (lane >= o) v += n;
    }
    if (lane == 31) sw[wid] = v;
    __syncthreads();
    if (wid == 0) {
        int t = sw[lane];
#pragma unroll
        for (int o = 1; o < 32; o <<= 1) {
            int n = __shfl_up_sync(0xffffffffu, t, o);
            if (lane >= o) t += n;
        }
        sw[lane] = t;
    }
    __syncthreads();
    int incl = v + (wid ? sw[wid - 1] : 0);
    if (gi < N_NODES) g_off[gi] = incl - val;
    if (tid == SCAN_BLK - 1) g_bsum[blockIdx.x] = incl;
}

__global__ void scan2_kernel() {
    __shared__ int wsum[4];
    int t = threadIdx.x;
    int orig = (t < SCAN_NBLK) ? g_bsum[t] : 0;
    int v = orig;
    int lane = t & 31, wid = t >> 5;
#pragma unroll
    for (int o = 1; o < 32; o <<= 1) {
        int n = __shfl_up_sync(0xffffffffu, v, o);
        if (lane >= o) v += n;
    }
    if (lane == 31) wsum[wid] = v;
    __syncthreads();
    if (t == 0) {
        int run = 0;
#pragma unroll
        for (int i = 0; i < 4; i++) { int x = wsum[i]; wsum[i] = run; run += x; }
    }
    __syncthreads();
    if (t < SCAN_NBLK) g_bsum[t] = v - orig + wsum[wid];
}

__global__ void scan3_kernel() {
    int gi = blockIdx.x * blockDim.x + threadIdx.x;
    if (gi < N_NODES) {
        int o = g_off[gi] + g_bsum[gi >> 10];
        g_off[gi] = o;
        g_cur[gi] = o;
    }
    if (gi == N_NODES) g_off[N_NODES] = N_EDGES;
}

__global__ void fill_kernel() {
    int e = blockIdx.x * blockDim.x + threadIdx.x;
    if (e < N_EDGES) {
        int s = g_src[e];
        int d = g_dst[e];
        int pos = atomicAdd(&g_cur[d], 1);
        g_edge[pos] = make_int2(s, __float_as_int(g_dinv[s] * g_dinv[d]));
    }
}

// ---------------- fp16 tensor-core GEMM (m16n8k16, cp.async + ldmatrix) -----------
__device__ __forceinline__ void mma_f16(float& c0, float& c1, float& c2, float& c3,
                                        uint32_t a0, uint32_t a1, uint32_t a2, uint32_t a3,
                                        uint32_t b0, uint32_t b1) {
    asm volatile(
        "mma.sync.aligned.m16n8k16.row.col.f32.f16.f16.f32 "
        "{%0,%1,%2,%3}, {%4,%5,%6,%7}, {%8,%9}, {%0,%1,%2,%3};"
        : "+f"(c0), "+f"(c1), "+f"(c2), "+f"(c3)
        : "r"(a0), "r"(a1), "r"(a2), "r"(a3), "r"(b0), "r"(b1));
}

__device__ __forceinline__ uint32_t cvta_smem(const void* p) {
    uint32_t a;
    asm("{ .reg .u64 t; cvta.to.shared.u64 t, %1; cvt.u32.u64 %0, t; }" : "=r"(a) : "l"(p));
    return a;
}

#define LDMX4(r0, r1, r2, r3, addr) \
    asm volatile("ldmatrix.sync.aligned.m8n8.x4.shared.b16 {%0,%1,%2,%3}, [%4];" \
                 : "=r"(r0), "=r"(r1), "=r"(r2), "=r"(r3) : "r"(addr))

#define CP_ASYNC16(dst, src) \
    asm volatile("cp.async.cg.shared.global [%0], [%1], 16;" :: "r"(dst), "l"(src))
#define CP_COMMIT() asm volatile("cp.async.commit_group;")
#define CP_WAIT(n)  asm volatile("cp.async.wait_group %0;" :: "n"(n))

// C[M,BN](fp16) = A[M,K](fp16) @ Wt[BN,K](fp16, N-major)
template <int BN, int K>
__global__ void __launch_bounds__(128 * (BN / 32), 2)
h16gemm_kernel(const __half* __restrict__ Ah, const __half* __restrict__ Wt,
               __half* __restrict__ C, int M) {
    constexpr int BM = 128, BK = 32;
    constexpr int SK = BK + 8;              // 40 halves -> 80B row stride, bank-clean
    constexpr int WARPS_N = BN / 32;
    constexpr int THREADS = 128 * WARPS_N;
    constexpr int AS1 = BM * SK;            // halves per A stage
    constexpr int BS1 = BN * SK;
    constexpr int NT = K / BK;
    constexpr int A_IT = BM * (BK / 8) / THREADS;
    constexpr int B_IT = (BN * (BK / 8) / THREADS > 0) ? BN * (BK / 8) / THREADS : 1;

    extern __shared__ __half smh[];

    int tid  = threadIdx.x;
    int warp = tid >> 5;
    int lane = tid & 31;
    int wm = warp / WARPS_N;
    int wn = warp % WARPS_N;
    int g = lane >> 2;
    int t = lane & 3;
    int block_row = blockIdx.x * BM;

    int l8 = lane & 7;
    int lb1 = (lane >> 3) & 1;
    int lb2 = lane >> 4;

    uint32_t As_u = cvta_smem(smh);                    // [2][AS1]
    uint32_t Bs_u = As_u + 2 * AS1 * 2;                // [2][BS1] (byte offset)

    float acc[2][4][4];
#pragma unroll
    for (int mi = 0; mi < 2; mi++)
#pragma unroll
        for (int ni = 0; ni < 4; ni++)
#pragma unroll
            for (int r = 0; r < 4; r++) acc[mi][ni][r] = 0.f;

    auto load_async = [&](int kt, int buf) {
        int k0 = kt * BK;
#pragma unroll
        for (int i = 0; i < A_IT; i++) {
            int idx = tid + i * THREADS;
            int r = idx >> 2;
            int c8 = (idx & 3) << 3;
            int gr = block_row + r;
            if (gr >= M) gr = 0;   // clamp; garbage rows masked in epilogue
            const __half* src = Ah + (size_t)gr * K + k0 + c8;
            uint32_t dst = As_u + (uint32_t)((buf * AS1 + r * SK + c8) * 2);
            CP_ASYNC16(dst, src);
        }
#pragma unroll
        for (int i = 0; i < B_IT; i++) {
            int idx = tid + i * THREADS;
            int n = idx >> 2;
            int c8 = (idx & 3) << 3;
            const __half* src = Wt + (size_t)n * K + k0 + c8;
            uint32_t dst = Bs_u + (uint32_t)((buf * BS1 + n * SK + c8) * 2);
            CP_ASYNC16(dst, src);
        }
        CP_COMMIT();
    };

    auto compute = [&](int buf) {
        uint32_t Abase = As_u + buf * (AS1 * 2);
        uint32_t Bbase = Bs_u + buf * (BS1 * 2);
#pragma unroll
        for (int kk = 0; kk < BK; kk += 16) {
            uint32_t a[2][4];
#pragma unroll
            for (int mi = 0; mi < 2; mi++) {
                uint32_t ad = Abase +
                    (uint32_t)(((wm * 32 + mi * 16 + lb1 * 8 + l8) * SK + lb2 * 8 + kk) * 2);
                LDMX4(a[mi][0], a[mi][1], a[mi][2], a[mi][3], ad);
            }
            uint32_t b[4][2];
#pragma unroll
            for (int p = 0; p < 2; p++) {
                uint32_t bd = Bbase +
                    (uint32_t)(((wn * 32 + p * 16 + lb2 * 8 + l8) * SK + lb1 * 8 + kk) * 2);
                uint32_t r0, r1, r2, r3;
                LDMX4(r0, r1, r2, r3, bd);
                b[2 * p][0] = r0; b[2 * p][1] = r1;
                b[2 * p + 1][0] = r2; b[2 * p + 1][1] = r3;
            }
#pragma unroll
            for (int mi = 0; mi < 2; mi++)
#pragma unroll
                for (int ni = 0; ni < 4; ni++)
                    mma_f16(acc[mi][ni][0], acc[mi][ni][1], acc[mi][ni][2], acc[mi][ni][3],
                            a[mi][0], a[mi][1], a[mi][2], a[mi][3],
                            b[ni][0], b[ni][1]);
        }
    };

    load_async(0, 0);
#pragma unroll
    for (int kt = 0; kt < NT; kt++) {
        if (kt + 1 < NT) {
            load_async(kt + 1, (kt + 1) & 1);
            CP_WAIT(1);
        } else {
            CP_WAIT(0);
        }
        __syncthreads();
        compute(kt & 1);
        __syncthreads();   // protect buffer reuse by next iteration's cp.async
    }

#pragma unroll
    for (int mi = 0; mi < 2; mi++) {
        int r0 = block_row + wm * 32 + mi * 16 + g;
        int r1 = r0 + 8;
#pragma unroll
        for (int ni = 0; ni < 4; ni++) {
            int c = wn * 32 + ni * 8 + 2 * t;
            if (r0 < M)
                *(__half2*)(C + (size_t)r0 * BN + c) = __floats2half2_rn(acc[mi][ni][0], acc[mi][ni][1]);
            if (r1 < M)
                *(__half2*)(C + (size_t)r1 * BN + c) = __floats2half2_rn(acc[mi][ni][2], acc[mi][ni][3]);
        }
    }
}

// ---------------- aggregation (warp-per-node, smem edge staging, 8-wide MLP) -------
__device__ __forceinline__ void fma_h8(float* acc, uint2 v, float w) {
    float2 f0 = __half22float2(*(const __half2*)&v.x);
    float2 f1 = __half22float2(*(const __half2*)&v.y);
    acc[0] = fmaf(w, f0.x, acc[0]); acc[1] = fmaf(w, f0.y, acc[1]);
    acc[2] = fmaf(w, f1.x, acc[2]); acc[3] = fmaf(w, f1.y, acc[3]);
}

template <int F>
__global__ void agg_kernel(const __half* __restrict__ tmp, const float* __restrict__ bias,
                           __half* __restrict__ out) {
    __shared__ int2 se[8][32];                 // per-warp edge staging
    int wslot = threadIdx.x >> 5;
    int warp = blockIdx.x * (blockDim.x >> 5) + wslot;
    if (warp >= N_NODES) return;
    int lane = threadIdx.x & 31;
    float di = g_dinv[warp];
    float sw = di * di;
    int beg = g_off[warp], end = g_off[warp + 1];

    float acc[4];
    if constexpr (F == 128) {
        uint2 v0 = ((const uint2*)(tmp + (size_t)warp * F))[lane];
        float2 a0 = __half22float2(*(const __half2*)&v0.x);
        float2 a1 = __half22float2(*(const __half2*)&v0.y);
        acc[0] = a0.x * sw; acc[1] = a0.y * sw; acc[2] = a1.x * sw; acc[3] = a1.y * sw;
    } else if constexpr (F == 64) {
        float2 a = __half22float2(((const __half2*)(tmp + (size_t)warp * F))[lane]);
        acc[0] = a.x * sw; acc[1] = a.y * sw;
    } else {
        acc[0] = __half2float(tmp[(size_t)warp * F + lane]) * sw;
    }

    for (int e = beg; e < end; e += 32) {
        int cnt = min(32, end - e);
        __syncwarp();
        if (lane < cnt) se[wslot][lane] = g_edge[e + lane];
        __syncwarp();
        int t = 0;
        if constexpr (F == 128) {
            for (; t + 8 <= cnt; t += 8) {
                int2 q0 = se[wslot][t];     int2 q1 = se[wslot][t + 1];
                int2 q2 = se[wslot][t + 2]; int2 q3 = se[wslot][t + 3];
                int2 q4 = se[wslot][t + 4]; int2 q5 = se[wslot][t + 5];
                int2 q6 = se[wslot][t + 6]; int2 q7 = se[wslot][t + 7];
                uint2 v0 = ((const uint2*)(tmp + (size_t)q0.x * F))[lane];
                uint2 v1 = ((const uint2*)(tmp + (size_t)q1.x * F))[lane];
                uint2 v2 = ((const uint2*)(tmp + (size_t)q2.x * F))[lane];
                uint2 v3 = ((const uint2*)(tmp + (size_t)q3.x * F))[lane];
                uint2 v4 = ((const uint2*)(tmp + (size_t)q4.x * F))[lane];
                uint2 v5 = ((const uint2*)(tmp + (size_t)q5.x * F))[lane];
                uint2 v6 = ((const uint2*)(tmp + (size_t)q6.x * F))[lane];
                uint2 v7 = ((const uint2*)(tmp + (size_t)q7.x * F))[lane];
                fma_h8(acc, v0, __int_as_float(q0.y));
                fma_h8(acc, v1, __int_as_float(q1.y));
                fma_h8(acc, v2, __int_as_float(q2.y));
                fma_h8(acc, v3, __int_as_float(q3.y));
                fma_h8(acc, v4, __int_as_float(q4.y));
                fma_h8(acc, v5, __int_as_float(q5.y));
                fma_h8(acc, v6, __int_as_float(q6.y));
                fma_h8(acc, v7, __int_as_float(q7.y));
            }
            for (; t < cnt; t++) {
                int2 q = se[wslot][t];
                uint2 v = ((const uint2*)(tmp + (size_t)q.x * F))[lane];
                fma_h8(acc, v, __int_as_float(q.y));
            }
        } else if constexpr (F == 64) {
            for (; t + 8 <= cnt; t += 8) {
#pragma unroll
                for (int u = 0; u < 8; u++) {
                    int2 q = se[wslot][t + u];
                    float2 v = __half22float2(((const __half2*)(tmp + (size_t)q.x * F))[lane]);
                    float w = __int_as_float(q.y);
                    acc[0] = fmaf(w, v.x, acc[0]); acc[1] = fmaf(w, v.y, acc[1]);
                }
            }
            for (; t < cnt; t++) {
                int2 q = se[wslot][t];
                float2 v = __half22float2(((const __half2*)(tmp + (size_t)q.x * F))[lane]);
                float w = __int_as_float(q.y);
                acc[0] = fmaf(w, v.x, acc[0]); acc[1] = fmaf(w, v.y, acc[1]);
            }
        } else {
            for (; t + 8 <= cnt; t += 8) {
#pragma unroll
                for (int u = 0; u < 8; u++) {
                    int2 q = se[wslot][t + u];
                    float v = __half2float(tmp[(size_t)q.x * F + lane]);
                    acc[0] = fmaf(__int_as_float(q.y), v, acc[0]);
                }
            }
            for (; t < cnt; t++) {
                int2 q = se[wslot][t];
                float v = __half2float(tmp[(size_t)q.x * F + lane]);
                acc[0] = fmaf(__int_as_float(q.y), v, acc[0]);
            }
        }
    }

    if constexpr (F == 128) {
        float4 b = ((const float4*)bias)[lane];
        acc[0] = fmaxf(acc[0] + b.x, 0.f); acc[1] = fmaxf(acc[1] + b.y, 0.f);
        acc[2] = fmaxf(acc[2] + b.z, 0.f); acc[3] = fmaxf(acc[3] + b.w, 0.f);
        uint2 ov;
        *(__half2*)&ov.x = __floats2half2_rn(acc[0], acc[1]);
        *(__half2*)&ov.y = __floats2half2_rn(acc[2], acc[3]);
        ((uint2*)(out + (size_t)warp * F))[lane] = ov;
    } else if constexpr (F == 64) {
        float2 b = ((const float2*)bias)[lane];
        acc[0] = fmaxf(acc[0] + b.x, 0.f); acc[1] = fmaxf(acc[1] + b.y, 0.f);
        ((__half2*)(out + (size_t)warp * F))[lane] = __floats2half2_rn(acc[0], acc[1]);
    } else {
        float r = fmaxf(acc[0] + bias[lane], 0.f);
        out[(size_t)warp * F + lane] = __float2half_rn(r);
    }
}

// ---------------- global mean pool (batch is sorted) ----------------
__global__ void pool_kernel(const __half* __restrict__ h) {
    __shared__ float sp[NGRAPHS * 32];
    __shared__ int   sc[NGRAPHS];
    int tid = threadIdx.x;
    for (int i = tid; i < NGRAPHS * 32; i += 256) sp[i] = 0.f;
    for (int i = tid; i < NGRAPHS; i += 256) sc[i] = 0;
    __syncthreads();
    int wid = tid >> 5, lane = tid & 31;
    int base = blockIdx.x * 1024;
    for (int it = 0; it < 128; it++) {
        int node = base + it * 8 + wid;
        if (node < N_NODES) {
            int b = g_batch[node];
            atomicAdd(&sp[b * 32 + lane], __half2float(h[(size_t)node * 32 + lane]));
            if (lane == 0) atomicAdd(&sc[b], 1);
        }
    }
    __syncthreads();
    for (int i = tid; i < NGRAPHS * 32; i += 256) {
        float v = sp[i];
        if (v != 0.f) atomicAdd(&g_pool[i], v);
    }
    for (int i = tid; i < NGRAPHS; i += 256)
        if (sc[i]) atomicAdd(&g_cnt[i], sc[i]);
}

// ---------------- final FC ----------------
__global__ void fc_kernel(const float* __restrict__ Wfc, const float* __restrict__ bfc,
                          float* __restrict__ out) {
    int tid = threadIdx.x;
    if (tid < NGRAPHS * 10) {
        int g = tid / 10, c = tid % 10;
        float cnt = fmaxf((float)g_cnt[g], 1.f);
        float s = bfc[c];
#pragma unroll
        for (int k = 0; k < 32; k++)
            s += (g_pool[g * 32 + k] / cnt) * Wfc[k * 10 + c];
        out[tid] = s;
    }
}

// ---------------- launch ----------------
extern "C" void kernel_launch(void* const* d_in, const int* in_sizes, int n_in,
                              void* d_out, int out_size) {
    const float* x        = (const float*)d_in[0];
    const int*   ei_words = (const int*)d_in[1];
    const int*   b_words  = (const int*)d_in[2];
    const float* W1 = (const float*)d_in[3];  const float* b1 = (const float*)d_in[4];
    const float* W2 = (const float*)d_in[5];  const float* b2 = (const float*)d_in[6];
    const float* W3 = (const float*)d_in[7];  const float* b3 = (const float*)d_in[8];
    const float* W4 = (const float*)d_in[9];  const float* b4 = (const float*)d_in[10];
    const float* W5 = (const float*)d_in[11]; const float* b5 = (const float*)d_in[12];
    const float* Wfc = (const float*)d_in[13]; const float* bfc = (const float*)d_in[14];
    float* out = (float*)d_out;

    void *p_tmp, *p_A, *p_B, *p_wh;
    cudaGetSymbolAddress(&p_tmp, g_tmp);
    cudaGetSymbolAddress(&p_A, g_bufA);
    cudaGetSymbolAddress(&p_B, g_bufB);
    cudaGetSymbolAddress(&p_wh, g_wh);
    __half* tmp  = (__half*)p_tmp;
    __half* bufA = (__half*)p_A;
    __half* bufB = (__half*)p_B;
    const __half* wh = (const __half*)p_wh;

    const int SM128 = 2 * (128 + 128) * 40 * 2;  // 40960
    const int SM64  = 2 * (128 + 64)  * 40 * 2;  // 30720
    const int SM32  = 2 * (128 + 32)  * 40 * 2;  // 25600

    const int GEMM_GRID = (N_NODES + 127) / 128;  // 782
    const int AGG_GRID  = (N_NODES + 7) / 8;      // 12500 (warp-per-node, 8 warps/blk)

    // ingestion + weight/feature preconvert; layer-1 GEMM early (independent of CSR)
    detect_kernel<<<1, 256>>>(ei_words);
    init_kernel<<<391, 256>>>();
    convert_w<<<(59392 + 255) / 256, 256>>>(W1, W2, W3, W4, W5);
    convert_x<<<(N_NODES * 128 / 8 + 255) / 256, 256>>>(x, bufB);
    h16gemm_kernel<128, 128><<<GEMM_GRID, 512, SM128>>>(bufB, wh, tmp, N_NODES);
    convert_edges<<<(N_EDGES + 255) / 256, 256>>>(ei_words, b_words);
    scan1_kernel<<<SCAN_NBLK, SCAN_BLK>>>();
    scan2_kernel<<<1, 128>>>();
    scan3_kernel<<<(N_NODES + 1 + 255) / 256, 256>>>();
    fill_kernel<<<(N_EDGES + 255) / 256, 256>>>();

    // layer 1 aggregation
    agg_kernel<128><<<AGG_GRID, 256>>>(tmp, b1, bufA);
    // layer 2
    h16gemm_kernel<128, 128><<<GEMM_GRID, 512, SM128>>>(bufA, wh + 16384, tmp, N_NODES);
    agg_kernel<128><<<AGG_GRID, 256>>>(tmp, b2, bufB);
    // layer 3
    h16gemm_kernel<128, 128><<<GEMM_GRID, 512, SM128>>>(bufB, wh + 32768, tmp, N_NODES);
    agg_kernel<128><<<AGG_GRID, 256>>>(tmp, b3, bufA);
    // layer 4: 128 -> 64
    h16gemm_kernel<64, 128><<<GEMM_GRID, 256, SM64>>>(bufA, wh + 49152, tmp, N_NODES);
    agg_kernel<64><<<AGG_GRID, 256>>>(tmp, b4, bufB);
    // layer 5: 64 -> 32
    h16gemm_kernel<32, 64><<<GEMM_GRID, 128, SM32>>>(bufB, wh + 57344, tmp, N_NODES);
    agg_kernel<32><<<AGG_GRID, 256>>>(tmp, b5, bufA);

    // pool + FC
    pool_kernel<<<(N_NODES + 1023) / 1024, 256>>>(bufA);
    fc_kernel<<<1, 640>>>(Wfc, bfc, out);
}

// round 14
// speedup vs baseline: 1.0679x; 1.0679x over previous
#include <cuda_runtime.h>
#include <cuda_fp16.h>
#include <math.h>
#include <stdint.h>

#define N_NODES 100000
#define N_EDGES 1600000
#define NGRAPHS 64
#define SCAN_BLK 1024
#define SCAN_NBLK ((N_NODES + SCAN_BLK - 1) / SCAN_BLK)  // 98

// ---------------- device scratch (static globals; no allocation) ----------------
__device__ __align__(16) __half g_tmp [(size_t)N_NODES * 128];
__device__ __align__(16) __half g_bufA[(size_t)N_NODES * 128];
__device__ __align__(16) __half g_bufB[(size_t)N_NODES * 128];
// fp16 weights, transposed to [N][K]: W1@0, W2@16384, W3@32768, W4@49152, W5@57344
__device__ __align__(16) __half g_wh[59392];
__device__ int   g_batch[N_NODES];
__device__ int   g_is64;
__device__ int   g_deg[N_NODES];
__device__ float g_dinv[N_NODES];
__device__ int   g_off[N_NODES + 1];
__device__ int   g_cur[N_NODES];
__device__ __align__(8) int2 g_edge[N_EDGES];  // (src, __float_as_int(norm))
__device__ int   g_bsum[SCAN_NBLK];
__device__ float g_pool[NGRAPHS * 32];
__device__ int   g_cnt [NGRAPHS];

// ---------------- dtype detection (parallel) + conversion ----------------
__global__ void detect_kernel(const int* __restrict__ w) {
    int i = threadIdx.x;                       // 256 threads
    int v = w[2 * i + 1];
    int any = __syncthreads_or(v != 0);
    if (i == 0) g_is64 = (any == 0);
}

__global__ void init_kernel() {
    int i = blockIdx.x * blockDim.x + threadIdx.x;
    if (i < N_NODES) g_deg[i] = 1;                 // self loop
    if (i < NGRAPHS * 32) g_pool[i] = 0.f;
    if (i < NGRAPHS) g_cnt[i] = 0;
}

// fused: degree histogram (dst only) + batch convert
__global__ void convert_edges(const int* __restrict__ w, const int* __restrict__ bw) {
    int e = blockIdx.x * blockDim.x + threadIdx.x;
    if (e < N_EDGES) {
        int d = g_is64 ? w[2 * (N_EDGES + e)] : w[N_EDGES + e];
        atomicAdd(&g_deg[d], 1);
    }
    if (e < N_NODES) g_batch[e] = g_is64 ? bw[2 * e] : bw[e];
}

// Preconvert all weights to fp16, transposed [N][K]
__global__ void convert_w(const float* __restrict__ W1, const float* __restrict__ W2,
                          const float* __restrict__ W3, const float* __restrict__ W4,
                          const float* __restrict__ W5) {
    int i = blockIdx.x * blockDim.x + threadIdx.x;
    if (i < 16384) {
        int n = i >> 7, k = i & 127;
        g_wh[i] = __float2half(W1[k * 128 + n]);
    } else if (i < 32768) {
        int l = i - 16384; int n = l >> 7, k = l & 127;
        g_wh[i] = __float2half(W2[k * 128 + n]);
    } else if (i < 49152) {
        int l = i - 32768; int n = l >> 7, k = l & 127;
        g_wh[i] = __float2half(W3[k * 128 + n]);
    } else if (i < 57344) {
        int l = i - 49152; int n = l >> 7, k = l & 127;
        g_wh[i] = __float2half(W4[k * 64 + n]);
    } else if (i < 59392) {
        int l = i - 57344; int n = l >> 6, k = l & 63;
        g_wh[i] = __float2half(W5[k * 32 + n]);
    }
}

// ---------------- CSR offsets: block scan (fused dinv) ----------------
__global__ void scan1_kernel() {
    __shared__ int sw[32];
    int tid = threadIdx.x;
    int gi = blockIdx.x * SCAN_BLK + tid;
    int deg = (gi < N_NODES) ? g_deg[gi] : 1;
    if (gi < N_NODES) g_dinv[gi] = rsqrtf((float)deg);
    int val = deg - 1;
    if (gi >= N_NODES) val = 0;
    int v = val;
    int lane = tid & 31, wid = tid >> 5;
#pragma unroll
    for (int o = 1; o < 32; o <<= 1) {
        int n = __shfl_up_sync(0xffffffffu, v, o);
        if (lane >= o) v += n;
    }
    if (lane == 31) sw[wid] = v;
    __syncthreads();
    if (wid == 0) {
        int t = sw[lane];
#pragma unroll
        for (int o = 1; o < 32; o <<= 1) {
            int n = __shfl_up_sync(0xffffffffu, t, o);
            if (lane >= o) t += n;
        }
        sw[lane] = t;
    }
    __syncthreads();
    int incl = v + (wid ? sw[wid - 1] : 0);
    if (gi < N_NODES) g_off[gi] = incl - val;
    if (tid == SCAN_BLK - 1) g_bsum[blockIdx.x] = incl;
}

__global__ void scan2_kernel() {
    __shared__ int wsum[4];
    int t = threadIdx.x;
    int orig = (t < SCAN_NBLK) ? g_bsum[t] : 0;
    int v = orig;
    int lane = t & 31, wid = t >> 5;
#pragma unroll
    for (int o = 1; o < 32; o <<= 1) {
        int n = __shfl_up_sync(0xffffffffu, v, o);
        if (lane >= o) v += n;
    }
    if (lane == 31) wsum[wid] = v;
    __syncthreads();
    if (t == 0) {
        int run = 0;
#pragma unroll
        for (int i = 0; i < 4; i++) { int x = wsum[i]; wsum[i] = run; run += x; }
    }
    __syncthreads();
    if (t < SCAN_NBLK) g_bsum[t] = v - orig + wsum[wid];
}

__global__ void scan3_kernel() {
    int gi = blockIdx.x * blockDim.x + threadIdx.x;
    if (gi < N_NODES) {
        int o = g_off[gi] + g_bsum[gi >> 10];
        g_off[gi] = o;
        g_cur[gi] = o;
    }
    if (gi == N_NODES) g_off[N_NODES] = N_EDGES;
}

// reads raw edge words directly (no src/dst intermediates)
__global__ void fill_kernel(const int* __restrict__ w) {
    int e = blockIdx.x * blockDim.x + threadIdx.x;
    if (e < N_EDGES) {
        int s, d;
        if (g_is64) { s = w[2 * e]; d = w[2 * (N_EDGES + e)]; }
        else        { s = w[e];     d = w[N_EDGES + e]; }
        int pos = atomicAdd(&g_cur[d], 1);
        g_edge[pos] = make_int2(s, __float_as_int(g_dinv[s] * g_dinv[d]));
    }
}

// ---------------- shared GEMM helpers ----------------
__device__ __forceinline__ void mma_f16(float& c0, float& c1, float& c2, float& c3,
                                        uint32_t a0, uint32_t a1, uint32_t a2, uint32_t a3,
                                        uint32_t b0, uint32_t b1) {
    asm volatile(
        "mma.sync.aligned.m16n8k16.row.col.f32.f16.f16.f32 "
        "{%0,%1,%2,%3}, {%4,%5,%6,%7}, {%8,%9}, {%0,%1,%2,%3};"
        : "+f"(c0), "+f"(c1), "+f"(c2), "+f"(c3)
        : "r"(a0), "r"(a1), "r"(a2), "r"(a3), "r"(b0), "r"(b1));
}

__device__ __forceinline__ uint32_t cvta_smem(const void* p) {
    uint32_t a;
    asm("{ .reg .u64 t; cvta.to.shared.u64 t, %1; cvt.u32.u64 %0, t; }" : "=r"(a) : "l"(p));
    return a;
}

#define LDMX4(r0, r1, r2, r3, addr) \
    asm volatile("ldmatrix.sync.aligned.m8n8.x4.shared.b16 {%0,%1,%2,%3}, [%4];" \
                 : "=r"(r0), "=r"(r1), "=r"(r2), "=r"(r3) : "r"(addr))

#define CP_ASYNC16(dst, src) \
    asm volatile("cp.async.cg.shared.global [%0], [%1], 16;" :: "r"(dst), "l"(src))
#define CP_COMMIT() asm volatile("cp.async.commit_group;")
#define CP_WAIT0()  asm volatile("cp.async.wait_group 0;")

// ---------------- layer-1 GEMM: R12-proven register-staged (fp32 A) ----------------
template <int BN, int K>
__global__ void __launch_bounds__(128 * (BN / 32), 2)
h16gemm_f32a_kernel(const float* __restrict__ Af, const __half* __restrict__ Wt,
                    __half* __restrict__ C, int M) {
    constexpr int BM = 128, BK = 32;
    constexpr int SK = BK + 8;
    constexpr int WARPS_N = BN / 32;
    constexpr int THREADS = 128 * WARPS_N;
    constexpr int AS1 = BM * SK;
    constexpr int BS1 = BN * SK;
    constexpr int NT = K / BK;
    constexpr int A_IT = BM * (BK / 8) / THREADS;
    constexpr int B_IT = (BN * (BK / 8) / THREADS > 0) ? BN * (BK / 8) / THREADS : 1;

    extern __shared__ __half smh[];
    __half* As = smh;
    __half* Bs = smh + 2 * AS1;

    int tid  = threadIdx.x;
    int warp = tid >> 5;
    int lane = tid & 31;
    int wm = warp / WARPS_N;
    int wn = warp % WARPS_N;
    int g = lane >> 2;
    int t = lane & 3;
    int block_row = blockIdx.x * BM;
    int l8 = lane & 7;
    int lb1 = (lane >> 3) & 1;
    int lb2 = lane >> 4;

    uint32_t As_u = cvta_smem(As);
    uint32_t Bs_u = cvta_smem(Bs);

    float acc[2][4][4];
#pragma unroll
    for (int mi = 0; mi < 2; mi++)
#pragma unroll
        for (int ni = 0; ni < 4; ni++)
#pragma unroll
            for (int r = 0; r < 4; r++) acc[mi][ni][r] = 0.f;

    uint4 ra[A_IT], rb[B_IT];

    auto load_tile = [&](int kt) {
        int k0 = kt * BK;
#pragma unroll
        for (int i = 0; i < A_IT; i++) {
            int idx = tid + i * THREADS;
            int r = idx >> 2;
            int c8 = (idx & 3) << 3;
            int gr = block_row + r;
            if (gr < M) {
                float4 f0 = *(const float4*)(Af + (size_t)gr * K + k0 + c8);
                float4 f1 = *(const float4*)(Af + (size_t)gr * K + k0 + c8 + 4);
                uint4 u;
                *(__half2*)&u.x = __floats2half2_rn(f0.x, f0.y);
                *(__half2*)&u.y = __floats2half2_rn(f0.z, f0.w);
                *(__half2*)&u.z = __floats2half2_rn(f1.x, f1.y);
                *(__half2*)&u.w = __floats2half2_rn(f1.z, f1.w);
                ra[i] = u;
            } else {
                ra[i] = make_uint4(0, 0, 0, 0);
            }
        }
#pragma unroll
        for (int i = 0; i < B_IT; i++) {
            int idx = tid + i * THREADS;
            int n = idx >> 2;
            int c8 = (idx & 3) << 3;
            rb[i] = *(const uint4*)(Wt + (size_t)n * K + k0 + c8);
        }
    };
    auto store_tile = [&](int buf) {
        __half* Ab = As + buf * AS1;
        __half* Bb = Bs + buf * BS1;
#pragma unroll
        for (int i = 0; i < A_IT; i++) {
            int idx = tid + i * THREADS;
            int r = idx >> 2;
            int c8 = (idx & 3) << 3;
            *(uint4*)(Ab + r * SK + c8) = ra[i];
        }
#pragma unroll
        for (int i = 0; i < B_IT; i++) {
            int idx = tid + i * THREADS;
            int n = idx >> 2;
            int c8 = (idx & 3) << 3;
            *(uint4*)(Bb + n * SK + c8) = rb[i];
        }
    };
    auto compute = [&](int buf) {
        uint32_t Abase = As_u + buf * (AS1 * 2);
        uint32_t Bbase = Bs_u + buf * (BS1 * 2);
#pragma unroll
        for (int kk = 0; kk < BK; kk += 16) {
            uint32_t a[2][4];
#pragma unroll
            for (int mi = 0; mi < 2; mi++) {
                uint32_t ad = Abase +
                    (uint32_t)(((wm * 32 + mi * 16 + lb1 * 8 + l8) * SK + lb2 * 8 + kk) * 2);
                LDMX4(a[mi][0], a[mi][1], a[mi][2], a[mi][3], ad);
            }
            uint32_t b[4][2];
#pragma unroll
            for (int p = 0; p < 2; p++) {
                uint32_t bd = Bbase +
                    (uint32_t)(((wn * 32 + p * 16 + lb2 * 8 + l8) * SK + lb1 * 8 + kk) * 2);
                uint32_t r0, r1, r2, r3;
                LDMX4(r0, r1, r2, r3, bd);
                b[2 * p][0] = r0; b[2 * p][1] = r1;
                b[2 * p + 1][0] = r2; b[2 * p + 1][1] = r3;
            }
#pragma unroll
            for (int mi = 0; mi < 2; mi++)
#pragma unroll
                for (int ni = 0; ni < 4; ni++)
                    mma_f16(acc[mi][ni][0], acc[mi][ni][1], acc[mi][ni][2], acc[mi][ni][3],
                            a[mi][0], a[mi][1], a[mi][2], a[mi][3],
                            b[ni][0], b[ni][1]);
        }
    };

    load_tile(0);
    store_tile(0);
    __syncthreads();
#pragma unroll
    for (int kt = 0; kt < NT; kt++) {
        if (kt + 1 < NT) load_tile(kt + 1);
        compute(kt & 1);
        if (kt + 1 < NT) {
            store_tile((kt + 1) & 1);
            __syncthreads();
        }
    }

#pragma unroll
    for (int mi = 0; mi < 2; mi++) {
        int r0 = block_row + wm * 32 + mi * 16 + g;
        int r1 = r0 + 8;
#pragma unroll
        for (int ni = 0; ni < 4; ni++) {
            int c = wn * 32 + ni * 8 + 2 * t;
            if (r0 < M)
                *(__half2*)(C + (size_t)r0 * BN + c) = __floats2half2_rn(acc[mi][ni][0], acc[mi][ni][1]);
            if (r1 < M)
                *(__half2*)(C + (size_t)r1 * BN + c) = __floats2half2_rn(acc[mi][ni][2], acc[mi][ni][3]);
        }
    }
}

// ---------------- fp16 layers: K-resident single-stage cp.async GEMM --------------
// Whole K dimension in smem; ALL loads issued async, ONE wait, ONE sync, then MMA.
template <int BN, int K>
__global__ void __launch_bounds__(128 * (BN / 32), 2)
h16gemm_res_kernel(const __half* __restrict__ Ah, const __half* __restrict__ Wt,
                   __half* __restrict__ C, int M) {
    constexpr int BM = 128;
    constexpr int SK = K + 8;               // conflict-free ldmatrix stride
    constexpr int WARPS_N = BN / 32;
    constexpr int THREADS = 128 * WARPS_N;
    constexpr int A_OPS = BM * (K / 8) / THREADS;
    constexpr int B_OPS = (BN * (K / 8) / THREADS > 0) ? BN * (K / 8) / THREADS : 1;
    constexpr int KV = K / 8;               // uint4 per row

    extern __shared__ __half smh[];
    __half* As = smh;                       // [BM][SK]
    __half* Bs = smh + BM * SK;             // [BN][SK]

    int tid  = threadIdx.x;
    int warp = tid >> 5;
    int lane = tid & 31;
    int wm = warp / WARPS_N;
    int wn = warp % WARPS_N;
    int g = lane >> 2;
    int t = lane & 3;
    int block_row = blockIdx.x * BM;
    int l8 = lane & 7;
    int lb1 = (lane >> 3) & 1;
    int lb2 = lane >> 4;

    uint32_t As_u = cvta_smem(As);
    uint32_t Bs_u = cvta_smem(Bs);

    // issue ALL loads asynchronously
#pragma unroll
    for (int i = 0; i < A_OPS; i++) {
        int idx = tid + i * THREADS;
        int r = idx / KV;
        int c8 = (idx % KV) << 3;
        int gr = block_row + r;
        if (gr >= M) gr = 0;                 // clamp; masked in epilogue
        CP_ASYNC16(As_u + (uint32_t)((r * SK + c8) * 2), Ah + (size_t)gr * K + c8);
    }
#pragma unroll
    for (int i = 0; i < B_OPS; i++) {
        int idx = tid + i * THREADS;
        int n = idx / KV;
        int c8 = (idx % KV) << 3;
        CP_ASYNC16(Bs_u + (uint32_t)((n * SK + c8) * 2), Wt + (size_t)n * K + c8);
    }
    CP_COMMIT();

    float acc[2][4][4];
#pragma unroll
    for (int mi = 0; mi < 2; mi++)
#pragma unroll
        for (int ni = 0; ni < 4; ni++)
#pragma unroll
            for (int r = 0; r < 4; r++) acc[mi][ni][r] = 0.f;

    CP_WAIT0();
    __syncthreads();

#pragma unroll
    for (int kk = 0; kk < K; kk += 16) {
        uint32_t a[2][4];
#pragma unroll
        for (int mi = 0; mi < 2; mi++) {
            uint32_t ad = As_u +
                (uint32_t)(((wm * 32 + mi * 16 + lb1 * 8 + l8) * SK + lb2 * 8 + kk) * 2);
            LDMX4(a[mi][0], a[mi][1], a[mi][2], a[mi][3], ad);
        }
        uint32_t b[4][2];
#pragma unroll
        for (int p = 0; p < 2; p++) {
            uint32_t bd = Bs_u +
                (uint32_t)(((wn * 32 + p * 16 + lb2 * 8 + l8) * SK + lb1 * 8 + kk) * 2);
            uint32_t r0, r1, r2, r3;
            LDMX4(r0, r1, r2, r3, bd);
            b[2 * p][0] = r0; b[2 * p][1] = r1;
            b[2 * p + 1][0] = r2; b[2 * p + 1][1] = r3;
        }
#pragma unroll
        for (int mi = 0; mi < 2; mi++)
#pragma unroll
            for (int ni = 0; ni < 4; ni++)
                mma_f16(acc[mi][ni][0], acc[mi][ni][1], acc[mi][ni][2], acc[mi][ni][3],
                        a[mi][0], a[mi][1], a[mi][2], a[mi][3],
                        b[ni][0], b[ni][1]);
    }

#pragma unroll
    for (int mi = 0; mi < 2; mi++) {
        int r0 = block_row + wm * 32 + mi * 16 + g;
        int r1 = r0 + 8;
#pragma unroll
        for (int ni = 0; ni < 4; ni++) {
            int c = wn * 32 + ni * 8 + 2 * t;
            if (r0 < M)
                *(__half2*)(C + (size_t)r0 * BN + c) = __floats2half2_rn(acc[mi][ni][0], acc[mi][ni][1]);
            if (r1 < M)
                *(__half2*)(C + (size_t)r1 * BN + c) = __floats2half2_rn(acc[mi][ni][2], acc[mi][ni][3]);
        }
    }
}

// ---------------- aggregation (warp-per-node, smem edge staging, 8-wide MLP) -------
__device__ __forceinline__ void fma_h8(float* acc, uint2 v, float w) {
    float2 f0 = __half22float2(*(const __half2*)&v.x);
    float2 f1 = __half22float2(*(const __half2*)&v.y);
    acc[0] = fmaf(w, f0.x, acc[0]); acc[1] = fmaf(w, f0.y, acc[1]);
    acc[2] = fmaf(w, f1.x, acc[2]); acc[3] = fmaf(w, f1.y, acc[3]);
}

template <int F>
__global__ void agg_kernel(const __half* __restrict__ tmp, const float* __restrict__ bias,
                           __half* __restrict__ out) {
    __shared__ int2 se[8][32];                 // per-warp edge staging
    int wslot = threadIdx.x >> 5;
    int warp = blockIdx.x * (blockDim.x >> 5) + wslot;
    if (warp >= N_NODES) return;
    int lane = threadIdx.x & 31;
    float di = g_dinv[warp];
    float sw = di * di;
    int beg = g_off[warp], end = g_off[warp + 1];

    float acc[4];
    if constexpr (F == 128) {
        uint2 v0 = ((const uint2*)(tmp + (size_t)warp * F))[lane];
        float2 a0 = __half22float2(*(const __half2*)&v0.x);
        float2 a1 = __half22float2(*(const __half2*)&v0.y);
        acc[0] = a0.x * sw; acc[1] = a0.y * sw; acc[2] = a1.x * sw; acc[3] = a1.y * sw;
    } else if constexpr (F == 64) {
        float2 a = __half22float2(((const __half2*)(tmp + (size_t)warp * F))[lane]);
        acc[0] = a.x * sw; acc[1] = a.y * sw;
    } else {
        acc[0] = __half2float(tmp[(size_t)warp * F + lane]) * sw;
    }

    for (int e = beg; e < end; e += 32) {
        int cnt = min(32, end - e);
        __syncwarp();
        if (lane < cnt) se[wslot][lane] = g_edge[e + lane];
        __syncwarp();
        int t = 0;
        if constexpr (F == 128) {
            for (; t + 8 <= cnt; t += 8) {
                int2 q0 = se[wslot][t];     int2 q1 = se[wslot][t + 1];
                int2 q2 = se[wslot][t + 2]; int2 q3 = se[wslot][t + 3];
                int2 q4 = se[wslot][t + 4]; int2 q5 = se[wslot][t + 5];
                int2 q6 = se[wslot][t + 6]; int2 q7 = se[wslot][t + 7];
                uint2 v0 = ((const uint2*)(tmp + (size_t)q0.x * F))[lane];
                uint2 v1 = ((const uint2*)(tmp + (size_t)q1.x * F))[lane];
                uint2 v2 = ((const uint2*)(tmp + (size_t)q2.x * F))[lane];
                uint2 v3 = ((const uint2*)(tmp + (size_t)q3.x * F))[lane];
                uint2 v4 = ((const uint2*)(tmp + (size_t)q4.x * F))[lane];
                uint2 v5 = ((const uint2*)(tmp + (size_t)q5.x * F))[lane];
                uint2 v6 = ((const uint2*)(tmp + (size_t)q6.x * F))[lane];
                uint2 v7 = ((const uint2*)(tmp + (size_t)q7.x * F))[lane];
                fma_h8(acc, v0, __int_as_float(q0.y));
                fma_h8(acc, v1, __int_as_float(q1.y));
                fma_h8(acc, v2, __int_as_float(q2.y));
                fma_h8(acc, v3, __int_as_float(q3.y));
                fma_h8(acc, v4, __int_as_float(q4.y));
                fma_h8(acc, v5, __int_as_float(q5.y));
                fma_h8(acc, v6, __int_as_float(q6.y));
                fma_h8(acc, v7, __int_as_float(q7.y));
            }
            for (; t < cnt; t++) {
                int2 q = se[wslot][t];
                uint2 v = ((const uint2*)(tmp + (size_t)q.x * F))[lane];
                fma_h8(acc, v, __int_as_float(q.y));
            }
        } else if constexpr (F == 64) {
            for (; t + 8 <= cnt; t += 8) {
#pragma unroll
                for (int u = 0; u < 8; u++) {
                    int2 q = se[wslot][t + u];
                    float2 v = __half22float2(((const __half2*)(tmp + (size_t)q.x * F))[lane]);
                    float w = __int_as_float(q.y);
                    acc[0] = fmaf(w, v.x, acc[0]); acc[1] = fmaf(w, v.y, acc[1]);
                }
            }
            for (; t < cnt; t++) {
                int2 q = se[wslot][t];
                float2 v = __half22float2(((const __half2*)(tmp + (size_t)q.x * F))[lane]);
                float w = __int_as_float(q.y);
                acc[0] = fmaf(w, v.x, acc[0]); acc[1] = fmaf(w, v.y, acc[1]);
            }
        } else {
            for (; t + 8 <= cnt; t += 8) {
#pragma unroll
                for (int u = 0; u < 8; u++) {
                    int2 q = se[wslot][t + u];
                    float v = __half2float(tmp[(size_t)q.x * F + lane]);
                    acc[0] = fmaf(__int_as_float(q.y), v, acc[0]);
                }
            }
            for (; t < cnt; t++) {
                int2 q = se[wslot][t];
                float v = __half2float(tmp[(size_t)q.x * F + lane]);
                acc[0] = fmaf(__int_as_float(q.y), v, acc[0]);
            }
        }
    }

    if constexpr (F == 128) {
        float4 b = ((const float4*)bias)[lane];
        acc[0] = fmaxf(acc[0] + b.x, 0.f); acc[1] = fmaxf(acc[1] + b.y, 0.f);
        acc[2] = fmaxf(acc[2] + b.z, 0.f); acc[3] = fmaxf(acc[3] + b.w, 0.f);
        uint2 ov;
        *(__half2*)&ov.x = __floats2half2_rn(acc[0], acc[1]);
        *(__half2*)&ov.y = __floats2half2_rn(acc[2], acc[3]);
        ((uint2*)(out + (size_t)warp * F))[lane] = ov;
    } else if constexpr (F == 64) {
        float2 b = ((const float2*)bias)[lane];
        acc[0] = fmaxf(acc[0] + b.x, 0.f); acc[1] = fmaxf(acc[1] + b.y, 0.f);
        ((__half2*)(out + (size_t)warp * F))[lane] = __floats2half2_rn(acc[0], acc[1]);
    } else {
        float r = fmaxf(acc[0] + bias[lane], 0.f);
        out[(size_t)warp * F + lane] = __float2half_rn(r);
    }
}

// ---------------- global mean pool (batch is sorted) ----------------
__global__ void pool_kernel(const __half* __restrict__ h) {
    __shared__ float sp[NGRAPHS * 32];
    __shared__ int   sc[NGRAPHS];
    int tid = threadIdx.x;
    for (int i = tid; i < NGRAPHS * 32; i += 256) sp[i] = 0.f;
    for (int i = tid; i < NGRAPHS; i += 256) sc[i] = 0;
    __syncthreads();
    int wid = tid >> 5, lane = tid & 31;
    int base = blockIdx.x * 1024;
    for (int it = 0; it < 128; it++) {
        int node = base + it * 8 + wid;
        if (node < N_NODES) {
            int b = g_batch[node];
            atomicAdd(&sp[b * 32 + lane], __half2float(h[(size_t)node * 32 + lane]));
            if (lane == 0) atomicAdd(&sc[b], 1);
        }
    }
    __syncthreads();
    for (int i = tid; i < NGRAPHS * 32; i += 256) {
        float v = sp[i];
        if (v != 0.f) atomicAdd(&g_pool[i], v);
    }
    for (int i = tid; i < NGRAPHS; i += 256)
        if (sc[i]) atomicAdd(&g_cnt[i], sc[i]);
}

// ---------------- final FC ----------------
__global__ void fc_kernel(const float* __restrict__ Wfc, const float* __restrict__ bfc,
                          float* __restrict__ out) {
    int tid = threadIdx.x;
    if (tid < NGRAPHS * 10) {
        int g = tid / 10, c = tid % 10;
        float cnt = fmaxf((float)g_cnt[g], 1.f);
        float s = bfc[c];
#pragma unroll
        for (int k = 0; k < 32; k++)
            s += (g_pool[g * 32 + k] / cnt) * Wfc[k * 10 + c];
        out[tid] = s;
    }
}

// ---------------- launch ----------------
extern "C" void kernel_launch(void* const* d_in, const int* in_sizes, int n_in,
                              void* d_out, int out_size) {
    const float* x        = (const float*)d_in[0];
    const int*   ei_words = (const int*)d_in[1];
    const int*   b_words  = (const int*)d_in[2];
    const float* W1 = (const float*)d_in[3];  const float* b1 = (const float*)d_in[4];
    const float* W2 = (const float*)d_in[5];  const float* b2 = (const float*)d_in[6];
    const float* W3 = (const float*)d_in[7];  const float* b3 = (const float*)d_in[8];
    const float* W4 = (const float*)d_in[9];  const float* b4 = (const float*)d_in[10];
    const float* W5 = (const float*)d_in[11]; const float* b5 = (const float*)d_in[12];
    const float* Wfc = (const float*)d_in[13]; const float* bfc = (const float*)d_in[14];
    float* out = (float*)d_out;

    void *p_tmp, *p_A, *p_B, *p_wh;
    cudaGetSymbolAddress(&p_tmp, g_tmp);
    cudaGetSymbolAddress(&p_A, g_bufA);
    cudaGetSymbolAddress(&p_B, g_bufB);
    cudaGetSymbolAddress(&p_wh, g_wh);
    __half* tmp  = (__half*)p_tmp;
    __half* bufA = (__half*)p_A;
    __half* bufB = (__half*)p_B;
    const __half* wh = (const __half*)p_wh;

    // smem sizes
    const int SM_L1   = 2 * (128 + 128) * 40 * 2;        // layer-1 staged kernel: 40960
    const int SMR_128 = (128 + 128) * (128 + 8) * 2;     // 69632
    const int SMR_64  = (128 + 64)  * (128 + 8) * 2;     // 52224
    const int SMR_32  = (128 + 32)  * (64 + 8)  * 2;     // 23040

    static bool attr_done = false;
    if (!attr_done) {
        cudaFuncSetAttribute(h16gemm_res_kernel<128, 128>,
                             cudaFuncAttributeMaxDynamicSharedMemorySize, SMR_128);
        cudaFuncSetAttribute(h16gemm_res_kernel<64, 128>,
                             cudaFuncAttributeMaxDynamicSharedMemorySize, SMR_64);
        attr_done = true;
    }

    const int GEMM_GRID = (N_NODES + 127) / 128;  // 782
    const int AGG_GRID  = (N_NODES + 7) / 8;      // 12500

    // ingestion + weight preconvert; layer-1 GEMM early (independent of CSR)
    detect_kernel<<<1, 256>>>(ei_words);
    init_kernel<<<391, 256>>>();
    convert_w<<<(59392 + 255) / 256, 256>>>(W1, W2, W3, W4, W5);
    h16gemm_f32a_kernel<128, 128><<<GEMM_GRID, 512, SM_L1>>>(x, wh, tmp, N_NODES);
    convert_edges<<<(N_EDGES + 255) / 256, 256>>>(ei_words, b_words);
    scan1_kernel<<<SCAN_NBLK, SCAN_BLK>>>();
    scan2_kernel<<<1, 128>>>();
    scan3_kernel<<<(N_NODES + 1 + 255) / 256, 256>>>();
    fill_kernel<<<(N_EDGES + 255) / 256, 256>>>(ei_words);

    // layer 1 aggregation
    agg_kernel<128><<<AGG_GRID, 256>>>(tmp, b1, bufA);
    // layer 2
    h16gemm_res_kernel<128, 128><<<GEMM_GRID, 512, SMR_128>>>(bufA, wh + 16384, tmp, N_NODES);
    agg_kernel<128><<<AGG_GRID, 256>>>(tmp, b2, bufB);
    // layer 3
    h16gemm_res_kernel<128, 128><<<GEMM_GRID, 512, SMR_128>>>(bufB, wh + 32768, tmp, N_NODES);
    agg_kernel<128><<<AGG_GRID, 256>>>(tmp, b3, bufA);
    // layer 4: 128 -> 64
    h16gemm_res_kernel<64, 128><<<GEMM_GRID, 256, SMR_64>>>(bufA, wh + 49152, tmp, N_NODES);
    agg_kernel<64><<<AGG_GRID, 256>>>(tmp, b4, bufB);
    // layer 5: 64 -> 32
    h16gemm_res_kernel<32, 64><<<GEMM_GRID, 128, SMR_32>>>(bufB, wh + 57344, tmp, N_NODES);
    agg_kernel<32><<<AGG_GRID, 256>>>(tmp, b5, bufA);

    // pool + FC
    pool_kernel<<<(N_NODES + 1023) / 1024, 256>>>(bufA);
    fc_kernel<<<1, 640>>>(Wfc, bfc, out);
}

// round 15
// speedup vs baseline: 1.0797x; 1.0110x over previous
#include <cuda_runtime.h>
#include <cuda_fp16.h>
#include <math.h>
#include <stdint.h>

#define N_NODES 100000
#define N_EDGES 1600000
#define NGRAPHS 64
#define SCAN_BLK 1024
#define SCAN_NBLK ((N_NODES + SCAN_BLK - 1) / SCAN_BLK)  // 98

// ---------------- device scratch (static globals; no allocation) ----------------
__device__ __align__(16) __half g_tmp [(size_t)N_NODES * 128];
__device__ __align__(16) __half g_bufA[(size_t)N_NODES * 128];
__device__ __align__(16) __half g_bufB[(size_t)N_NODES * 128];
// fp16 weights, transposed to [N][K]: W1@0, W2@16384, W3@32768, W4@49152, W5@57344
__device__ __align__(16) __half g_wh[59392];
__device__ int   g_batch[N_NODES];
__device__ int   g_is64;
__device__ int   g_deg[N_NODES];
__device__ float g_dinv[N_NODES];
__device__ int   g_off[N_NODES + 1];
__device__ int   g_cur[N_NODES];
__device__ __align__(8) int2 g_edge[N_EDGES];  // (src, __float_as_int(norm))
__device__ int   g_bsum[SCAN_NBLK];
__device__ float g_pool[NGRAPHS * 32];
__device__ int   g_cnt [NGRAPHS];

// ---------------- dtype detection (parallel) + conversion ----------------
__global__ void detect_kernel(const int* __restrict__ w) {
    int i = threadIdx.x;                       // 256 threads
    int v = w[2 * i + 1];
    int any = __syncthreads_or(v != 0);
    if (i == 0) g_is64 = (any == 0);
}

__global__ void init_kernel() {
    int i = blockIdx.x * blockDim.x + threadIdx.x;
    if (i < N_NODES) g_deg[i] = 1;                 // self loop
    if (i < NGRAPHS * 32) g_pool[i] = 0.f;
    if (i < NGRAPHS) g_cnt[i] = 0;
}

// fused: degree histogram (dst only) + batch convert
__global__ void convert_edges(const int* __restrict__ w, const int* __restrict__ bw) {
    int e = blockIdx.x * blockDim.x + threadIdx.x;
    if (e < N_EDGES) {
        int d = g_is64 ? w[2 * (N_EDGES + e)] : w[N_EDGES + e];
        atomicAdd(&g_deg[d], 1);
    }
    if (e < N_NODES) g_batch[e] = g_is64 ? bw[2 * e] : bw[e];
}

// Preconvert all weights to fp16, transposed [N][K]
__global__ void convert_w(const float* __restrict__ W1, const float* __restrict__ W2,
                          const float* __restrict__ W3, const float* __restrict__ W4,
                          const float* __restrict__ W5) {
    int i = blockIdx.x * blockDim.x + threadIdx.x;
    if (i < 16384) {
        int n = i >> 7, k = i & 127;
        g_wh[i] = __float2half(W1[k * 128 + n]);
    } else if (i < 32768) {
        int l = i - 16384; int n = l >> 7, k = l & 127;
        g_wh[i] = __float2half(W2[k * 128 + n]);
    } else if (i < 49152) {
        int l = i - 32768; int n = l >> 7, k = l & 127;
        g_wh[i] = __float2half(W3[k * 128 + n]);
    } else if (i < 57344) {
        int l = i - 49152; int n = l >> 7, k = l & 127;
        g_wh[i] = __float2half(W4[k * 64 + n]);
    } else if (i < 59392) {
        int l = i - 57344; int n = l >> 6, k = l & 63;
        g_wh[i] = __float2half(W5[k * 32 + n]);
    }
}

// ---------------- CSR offsets: block scan (fused dinv) ----------------
__global__ void scan1_kernel() {
    __shared__ int sw[32];
    int tid = threadIdx.x;
    int gi = blockIdx.x * SCAN_BLK + tid;
    int deg = (gi < N_NODES) ? g_deg[gi] : 1;
    if (gi < N_NODES) g_dinv[gi] = rsqrtf((float)deg);
    int val = deg - 1;
    if (gi >= N_NODES) val = 0;
    int v = val;
    int lane = tid & 31, wid = tid >> 5;
#pragma unroll
    for (int o = 1; o < 32; o <<= 1) {
        int n = __shfl_up_sync(0xffffffffu, v, o);
        if (lane >= o) v += n;
    }
    if (lane == 31) sw[wid] = v;
    __syncthreads();
    if (wid == 0) {
        int t = sw[lane];
#pragma unroll
        for (int o = 1; o < 32; o <<= 1) {
            int n = __shfl_up_sync(0xffffffffu, t, o);
            if (lane >= o) t += n;
        }
        sw[lane] = t;
    }
    __syncthreads();
    int incl = v + (wid ? sw[wid - 1] : 0);
    if (gi < N_NODES) g_off[gi] = incl - val;
    if (tid == SCAN_BLK - 1) g_bsum[blockIdx.x] = incl;
}

__global__ void scan2_kernel() {
    __shared__ int wsum[4];
    int t = threadIdx.x;
    int orig = (t < SCAN_NBLK) ? g_bsum[t] : 0;
    int v = orig;
    int lane = t & 31, wid = t >> 5;
#pragma unroll
    for (int o = 1; o < 32; o <<= 1) {
        int n = __shfl_up_sync(0xffffffffu, v, o);
        if (lane >= o) v += n;
    }
    if (lane == 31) wsum[wid] = v;
    __syncthreads();
    if (t == 0) {
        int run = 0;
#pragma unroll
        for (int i = 0; i < 4; i++) { int x = wsum[i]; wsum[i] = run; run += x; }
    }
    __syncthreads();
    if (t < SCAN_NBLK) g_bsum[t] = v - orig + wsum[wid];
}

__global__ void scan3_kernel() {
    int gi = blockIdx.x * blockDim.x + threadIdx.x;
    if (gi < N_NODES) {
        int o = g_off[gi] + g_bsum[gi >> 10];
        g_off[gi] = o;
        g_cur[gi] = o;
    }
    if (gi == N_NODES) g_off[N_NODES] = N_EDGES;
}

// reads raw edge words directly (no src/dst intermediates)
__global__ void fill_kernel(const int* __restrict__ w) {
    int e = blockIdx.x * blockDim.x + threadIdx.x;
    if (e < N_EDGES) {
        int s, d;
        if (g_is64) { s = w[2 * e]; d = w[2 * (N_EDGES + e)]; }
        else        { s = w[e];     d = w[N_EDGES + e]; }
        int pos = atomicAdd(&g_cur[d], 1);
        g_edge[pos] = make_int2(s, __float_as_int(g_dinv[s] * g_dinv[d]));
    }
}

// ---------------- shared GEMM helpers ----------------
__device__ __forceinline__ void mma_f16(float& c0, float& c1, float& c2, float& c3,
                                        uint32_t a0, uint32_t a1, uint32_t a2, uint32_t a3,
                                        uint32_t b0, uint32_t b1) {
    asm volatile(
        "mma.sync.aligned.m16n8k16.row.col.f32.f16.f16.f32 "
        "{%0,%1,%2,%3}, {%4,%5,%6,%7}, {%8,%9}, {%0,%1,%2,%3};"
        : "+f"(c0), "+f"(c1), "+f"(c2), "+f"(c3)
        : "r"(a0), "r"(a1), "r"(a2), "r"(a3), "r"(b0), "r"(b1));
}

__device__ __forceinline__ uint32_t cvta_smem(const void* p) {
    uint32_t a;
    asm("{ .reg .u64 t; cvta.to.shared.u64 t, %1; cvt.u32.u64 %0, t; }" : "=r"(a) : "l"(p));
    return a;
}

#define LDMX4(r0, r1, r2, r3, addr) \
    asm volatile("ldmatrix.sync.aligned.m8n8.x4.shared.b16 {%0,%1,%2,%3}, [%4];" \
                 : "=r"(r0), "=r"(r1), "=r"(r2), "=r"(r3) : "r"(addr))

#define CP_ASYNC16(dst, src) \
    asm volatile("cp.async.cg.shared.global [%0], [%1], 16;" :: "r"(dst), "l"(src))
#define CP_COMMIT() asm volatile("cp.async.commit_group;")
#define CP_WAIT0()  asm volatile("cp.async.wait_group 0;")

// ---------------- layer-1 GEMM: register-staged (fp32 A) ----------------
template <int BN, int K>
__global__ void __launch_bounds__(128 * (BN / 32), 2)
h16gemm_f32a_kernel(const float* __restrict__ Af, const __half* __restrict__ Wt,
                    __half* __restrict__ C, int M) {
    constexpr int BM = 128, BK = 32;
    constexpr int SK = BK + 8;
    constexpr int WARPS_N = BN / 32;
    constexpr int THREADS = 128 * WARPS_N;
    constexpr int AS1 = BM * SK;
    constexpr int BS1 = BN * SK;
    constexpr int NT = K / BK;
    constexpr int A_IT = BM * (BK / 8) / THREADS;
    constexpr int B_IT = (BN * (BK / 8) / THREADS > 0) ? BN * (BK / 8) / THREADS : 1;

    extern __shared__ __half smh[];
    __half* As = smh;
    __half* Bs = smh + 2 * AS1;

    int tid  = threadIdx.x;
    int warp = tid >> 5;
    int lane = tid & 31;
    int wm = warp / WARPS_N;
    int wn = warp % WARPS_N;
    int g = lane >> 2;
    int t = lane & 3;
    int block_row = blockIdx.x * BM;
    int l8 = lane & 7;
    int lb1 = (lane >> 3) & 1;
    int lb2 = lane >> 4;

    uint32_t As_u = cvta_smem(As);
    uint32_t Bs_u = cvta_smem(Bs);

    float acc[2][4][4];
#pragma unroll
    for (int mi = 0; mi < 2; mi++)
#pragma unroll
        for (int ni = 0; ni < 4; ni++)
#pragma unroll
            for (int r = 0; r < 4; r++) acc[mi][ni][r] = 0.f;

    uint4 ra[A_IT], rb[B_IT];

    auto load_tile = [&](int kt) {
        int k0 = kt * BK;
#pragma unroll
        for (int i = 0; i < A_IT; i++) {
            int idx = tid + i * THREADS;
            int r = idx >> 2;
            int c8 = (idx & 3) << 3;
            int gr = block_row + r;
            if (gr < M) {
                float4 f0 = *(const float4*)(Af + (size_t)gr * K + k0 + c8);
                float4 f1 = *(const float4*)(Af + (size_t)gr * K + k0 + c8 + 4);
                uint4 u;
                *(__half2*)&u.x = __floats2half2_rn(f0.x, f0.y);
                *(__half2*)&u.y = __floats2half2_rn(f0.z, f0.w);
                *(__half2*)&u.z = __floats2half2_rn(f1.x, f1.y);
                *(__half2*)&u.w = __floats2half2_rn(f1.z, f1.w);
                ra[i] = u;
            } else {
                ra[i] = make_uint4(0, 0, 0, 0);
            }
        }
#pragma unroll
        for (int i = 0; i < B_IT; i++) {
            int idx = tid + i * THREADS;
            int n = idx >> 2;
            int c8 = (idx & 3) << 3;
            rb[i] = *(const uint4*)(Wt + (size_t)n * K + k0 + c8);
        }
    };
    auto store_tile = [&](int buf) {
        __half* Ab = As + buf * AS1;
        __half* Bb = Bs + buf * BS1;
#pragma unroll
        for (int i = 0; i < A_IT; i++) {
            int idx = tid + i * THREADS;
            int r = idx >> 2;
            int c8 = (idx & 3) << 3;
            *(uint4*)(Ab + r * SK + c8) = ra[i];
        }
#pragma unroll
        for (int i = 0; i < B_IT; i++) {
            int idx = tid + i * THREADS;
            int n = idx >> 2;
            int c8 = (idx & 3) << 3;
            *(uint4*)(Bb + n * SK + c8) = rb[i];
        }
    };
    auto compute = [&](int buf) {
        uint32_t Abase = As_u + buf * (AS1 * 2);
        uint32_t Bbase = Bs_u + buf * (BS1 * 2);
#pragma unroll
        for (int kk = 0; kk < BK; kk += 16) {
            uint32_t a[2][4];
#pragma unroll
            for (int mi = 0; mi < 2; mi++) {
                uint32_t ad = Abase +
                    (uint32_t)(((wm * 32 + mi * 16 + lb1 * 8 + l8) * SK + lb2 * 8 + kk) * 2);
                LDMX4(a[mi][0], a[mi][1], a[mi][2], a[mi][3], ad);
            }
            uint32_t b[4][2];
#pragma unroll
            for (int p = 0; p < 2; p++) {
                uint32_t bd = Bbase +
                    (uint32_t)(((wn * 32 + p * 16 + lb2 * 8 + l8) * SK + lb1 * 8 + kk) * 2);
                uint32_t r0, r1, r2, r3;
                LDMX4(r0, r1, r2, r3, bd);
                b[2 * p][0] = r0; b[2 * p][1] = r1;
                b[2 * p + 1][0] = r2; b[2 * p + 1][1] = r3;
            }
#pragma unroll
            for (int mi = 0; mi < 2; mi++)
#pragma unroll
                for (int ni = 0; ni < 4; ni++)
                    mma_f16(acc[mi][ni][0], acc[mi][ni][1], acc[mi][ni][2], acc[mi][ni][3],
                            a[mi][0], a[mi][1], a[mi][2], a[mi][3],
                            b[ni][0], b[ni][1]);
        }
    };

    load_tile(0);
    store_tile(0);
    __syncthreads();
#pragma unroll
    for (int kt = 0; kt < NT; kt++) {
        if (kt + 1 < NT) load_tile(kt + 1);
        compute(kt & 1);
        if (kt + 1 < NT) {
            store_tile((kt + 1) & 1);
            __syncthreads();
        }
    }

#pragma unroll
    for (int mi = 0; mi < 2; mi++) {
        int r0 = block_row + wm * 32 + mi * 16 + g;
        int r1 = r0 + 8;
#pragma unroll
        for (int ni = 0; ni < 4; ni++) {
            int c = wn * 32 + ni * 8 + 2 * t;
            if (r0 < M)
                *(__half2*)(C + (size_t)r0 * BN + c) = __floats2half2_rn(acc[mi][ni][0], acc[mi][ni][1]);
            if (r1 < M)
                *(__half2*)(C + (size_t)r1 * BN + c) = __floats2half2_rn(acc[mi][ni][2], acc[mi][ni][3]);
        }
    }
}

// ---------------- fp16 layers: K-resident single-stage cp.async GEMM --------------
template <int BN, int K>
__global__ void __launch_bounds__(128 * (BN / 32), 2)
h16gemm_res_kernel(const __half* __restrict__ Ah, const __half* __restrict__ Wt,
                   __half* __restrict__ C, int M) {
    constexpr int BM = 128;
    constexpr int SK = K + 8;
    constexpr int WARPS_N = BN / 32;
    constexpr int THREADS = 128 * WARPS_N;
    constexpr int A_OPS = BM * (K / 8) / THREADS;
    constexpr int B_OPS = (BN * (K / 8) / THREADS > 0) ? BN * (K / 8) / THREADS : 1;
    constexpr int KV = K / 8;

    extern __shared__ __half smh[];
    __half* As = smh;
    __half* Bs = smh + BM * SK;

    int tid  = threadIdx.x;
    int warp = tid >> 5;
    int lane = tid & 31;
    int wm = warp / WARPS_N;
    int wn = warp % WARPS_N;
    int g = lane >> 2;
    int t = lane & 3;
    int block_row = blockIdx.x * BM;
    int l8 = lane & 7;
    int lb1 = (lane >> 3) & 1;
    int lb2 = lane >> 4;

    uint32_t As_u = cvta_smem(As);
    uint32_t Bs_u = cvta_smem(Bs);

#pragma unroll
    for (int i = 0; i < A_OPS; i++) {
        int idx = tid + i * THREADS;
        int r = idx / KV;
        int c8 = (idx % KV) << 3;
        int gr = block_row + r;
        if (gr >= M) gr = 0;
        CP_ASYNC16(As_u + (uint32_t)((r * SK + c8) * 2), Ah + (size_t)gr * K + c8);
    }
#pragma unroll
    for (int i = 0; i < B_OPS; i++) {
        int idx = tid + i * THREADS;
        int n = idx / KV;
        int c8 = (idx % KV) << 3;
        CP_ASYNC16(Bs_u + (uint32_t)((n * SK + c8) * 2), Wt + (size_t)n * K + c8);
    }
    CP_COMMIT();

    float acc[2][4][4];
#pragma unroll
    for (int mi = 0; mi < 2; mi++)
#pragma unroll
        for (int ni = 0; ni < 4; ni++)
#pragma unroll
            for (int r = 0; r < 4; r++) acc[mi][ni][r] = 0.f;

    CP_WAIT0();
    __syncthreads();

#pragma unroll
    for (int kk = 0; kk < K; kk += 16) {
        uint32_t a[2][4];
#pragma unroll
        for (int mi = 0; mi < 2; mi++) {
            uint32_t ad = As_u +
                (uint32_t)(((wm * 32 + mi * 16 + lb1 * 8 + l8) * SK + lb2 * 8 + kk) * 2);
            LDMX4(a[mi][0], a[mi][1], a[mi][2], a[mi][3], ad);
        }
        uint32_t b[4][2];
#pragma unroll
        for (int p = 0; p < 2; p++) {
            uint32_t bd = Bs_u +
                (uint32_t)(((wn * 32 + p * 16 + lb2 * 8 + l8) * SK + lb1 * 8 + kk) * 2);
            uint32_t r0, r1, r2, r3;
            LDMX4(r0, r1, r2, r3, bd);
            b[2 * p][0] = r0; b[2 * p][1] = r1;
            b[2 * p + 1][0] = r2; b[2 * p + 1][1] = r3;
        }
#pragma unroll
        for (int mi = 0; mi < 2; mi++)
#pragma unroll
            for (int ni = 0; ni < 4; ni++)
                mma_f16(acc[mi][ni][0], acc[mi][ni][1], acc[mi][ni][2], acc[mi][ni][3],
                        a[mi][0], a[mi][1], a[mi][2], a[mi][3],
                        b[ni][0], b[ni][1]);
    }

#pragma unroll
    for (int mi = 0; mi < 2; mi++) {
        int r0 = block_row + wm * 32 + mi * 16 + g;
        int r1 = r0 + 8;
#pragma unroll
        for (int ni = 0; ni < 4; ni++) {
            int c = wn * 32 + ni * 8 + 2 * t;
            if (r0 < M)
                *(__half2*)(C + (size_t)r0 * BN + c) = __floats2half2_rn(acc[mi][ni][0], acc[mi][ni][1]);
            if (r1 < M)
                *(__half2*)(C + (size_t)r1 * BN + c) = __floats2half2_rn(acc[mi][ni][2], acc[mi][ni][3]);
        }
    }
}

// ---------------- aggregation (warp-per-node, smem edge staging, 8-wide MLP) -------
__device__ __forceinline__ void fma_h8(float* acc, uint2 v, float w) {
    float2 f0 = __half22float2(*(const __half2*)&v.x);
    float2 f1 = __half22float2(*(const __half2*)&v.y);
    acc[0] = fmaf(w, f0.x, acc[0]); acc[1] = fmaf(w, f0.y, acc[1]);
    acc[2] = fmaf(w, f1.x, acc[2]); acc[3] = fmaf(w, f1.y, acc[3]);
}

template <int F>
__global__ void agg_kernel(const __half* __restrict__ tmp, const float* __restrict__ bias,
                           __half* __restrict__ out) {
    __shared__ int2 se[8][32];
    int wslot = threadIdx.x >> 5;
    int warp = blockIdx.x * (blockDim.x >> 5) + wslot;
    if (warp >= N_NODES) return;
    int lane = threadIdx.x & 31;
    float di = g_dinv[warp];
    float sw = di * di;
    int beg = g_off[warp], end = g_off[warp + 1];

    float acc[4];
    if constexpr (F == 128) {
        uint2 v0 = ((const uint2*)(tmp + (size_t)warp * F))[lane];
        float2 a0 = __half22float2(*(const __half2*)&v0.x);
        float2 a1 = __half22float2(*(const __half2*)&v0.y);
        acc[0] = a0.x * sw; acc[1] = a0.y * sw; acc[2] = a1.x * sw; acc[3] = a1.y * sw;
    } else if constexpr (F == 64) {
        float2 a = __half22float2(((const __half2*)(tmp + (size_t)warp * F))[lane]);
        acc[0] = a.x * sw; acc[1] = a.y * sw;
    } else {
        acc[0] = __half2float(tmp[(size_t)warp * F + lane]) * sw;
    }

    for (int e = beg; e < end; e += 32) {
        int cnt = min(32, end - e);
        __syncwarp();
        if (lane < cnt) se[wslot][lane] = g_edge[e + lane];
        __syncwarp();
        int t = 0;
        if constexpr (F == 128) {
            for (; t + 8 <= cnt; t += 8) {
                int2 q0 = se[wslot][t];     int2 q1 = se[wslot][t + 1];
                int2 q2 = se[wslot][t + 2]; int2 q3 = se[wslot][t + 3];
                int2 q4 = se[wslot][t + 4]; int2 q5 = se[wslot][t + 5];
                int2 q6 = se[wslot][t + 6]; int2 q7 = se[wslot][t + 7];
                uint2 v0 = ((const uint2*)(tmp + (size_t)q0.x * F))[lane];
                uint2 v1 = ((const uint2*)(tmp + (size_t)q1.x * F))[lane];
                uint2 v2 = ((const uint2*)(tmp + (size_t)q2.x * F))[lane];
                uint2 v3 = ((const uint2*)(tmp + (size_t)q3.x * F))[lane];
                uint2 v4 = ((const uint2*)(tmp + (size_t)q4.x * F))[lane];
                uint2 v5 = ((const uint2*)(tmp + (size_t)q5.x * F))[lane];
                uint2 v6 = ((const uint2*)(tmp + (size_t)q6.x * F))[lane];
                uint2 v7 = ((const uint2*)(tmp + (size_t)q7.x * F))[lane];
                fma_h8(acc, v0, __int_as_float(q0.y));
                fma_h8(acc, v1, __int_as_float(q1.y));
                fma_h8(acc, v2, __int_as_float(q2.y));
                fma_h8(acc, v3, __int_as_float(q3.y));
                fma_h8(acc, v4, __int_as_float(q4.y));
                fma_h8(acc, v5, __int_as_float(q5.y));
                fma_h8(acc, v6, __int_as_float(q6.y));
                fma_h8(acc, v7, __int_as_float(q7.y));
            }
            for (; t < cnt; t++) {
                int2 q = se[wslot][t];
                uint2 v = ((const uint2*)(tmp + (size_t)q.x * F))[lane];
                fma_h8(acc, v, __int_as_float(q.y));
            }
        } else if constexpr (F == 64) {
            for (; t + 8 <= cnt; t += 8) {
#pragma unroll
                for (int u = 0; u < 8; u++) {
                    int2 q = se[wslot][t + u];
                    float2 v = __half22float2(((const __half2*)(tmp + (size_t)q.x * F))[lane]);
                    float w = __int_as_float(q.y);
                    acc[0] = fmaf(w, v.x, acc[0]); acc[1] = fmaf(w, v.y, acc[1]);
                }
            }
            for (; t < cnt; t++) {
                int2 q = se[wslot][t];
                float2 v = __half22float2(((const __half2*)(tmp + (size_t)q.x * F))[lane]);
                float w = __int_as_float(q.y);
                acc[0] = fmaf(w, v.x, acc[0]); acc[1] = fmaf(w, v.y, acc[1]);
            }
        } else {
            for (; t + 8 <= cnt; t += 8) {
#pragma unroll
                for (int u = 0; u < 8; u++) {
                    int2 q = se[wslot][t + u];
                    float v = __half2float(tmp[(size_t)q.x * F + lane]);
                    acc[0] = fmaf(__int_as_float(q.y), v, acc[0]);
                }
            }
            for (; t < cnt; t++) {
                int2 q = se[wslot][t];
                float v = __half2float(tmp[(size_t)q.x * F + lane]);
                acc[0] = fmaf(__int_as_float(q.y), v, acc[0]);
            }
        }
    }

    if constexpr (F == 128) {
        float4 b = ((const float4*)bias)[lane];
        acc[0] = fmaxf(acc[0] + b.x, 0.f); acc[1] = fmaxf(acc[1] + b.y, 0.f);
        acc[2] = fmaxf(acc[2] + b.z, 0.f); acc[3] = fmaxf(acc[3] + b.w, 0.f);
        uint2 ov;
        *(__half2*)&ov.x = __floats2half2_rn(acc[0], acc[1]);
        *(__half2*)&ov.y = __floats2half2_rn(acc[2], acc[3]);
        ((uint2*)(out + (size_t)warp * F))[lane] = ov;
    } else if constexpr (F == 64) {
        float2 b = ((const float2*)bias)[lane];
        acc[0] = fmaxf(acc[0] + b.x, 0.f); acc[1] = fmaxf(acc[1] + b.y, 0.f);
        ((__half2*)(out + (size_t)warp * F))[lane] = __floats2half2_rn(acc[0], acc[1]);
    } else {
        float r = fmaxf(acc[0] + bias[lane], 0.f);
        out[(size_t)warp * F + lane] = __float2half_rn(r);
    }
}

// ---------------- global mean pool (batch is sorted) ----------------
__global__ void pool_kernel(const __half* __restrict__ h) {
    __shared__ float sp[NGRAPHS * 32];
    __shared__ int   sc[NGRAPHS];
    int tid = threadIdx.x;
    for (int i = tid; i < NGRAPHS * 32; i += 256) sp[i] = 0.f;
    for (int i = tid; i < NGRAPHS; i += 256) sc[i] = 0;
    __syncthreads();
    int wid = tid >> 5, lane = tid & 31;
    int base = blockIdx.x * 1024;
    for (int it = 0; it < 128; it++) {
        int node = base + it * 8 + wid;
        if (node < N_NODES) {
            int b = g_batch[node];
            atomicAdd(&sp[b * 32 + lane], __half2float(h[(size_t)node * 32 + lane]));
            if (lane == 0) atomicAdd(&sc[b], 1);
        }
    }
    __syncthreads();
    for (int i = tid; i < NGRAPHS * 32; i += 256) {
        float v = sp[i];
        if (v != 0.f) atomicAdd(&g_pool[i], v);
    }
    for (int i = tid; i < NGRAPHS; i += 256)
        if (sc[i]) atomicAdd(&g_cnt[i], sc[i]);
}

// ---------------- final FC ----------------
__global__ void fc_kernel(const float* __restrict__ Wfc, const float* __restrict__ bfc,
                          float* __restrict__ out) {
    int tid = threadIdx.x;
    if (tid < NGRAPHS * 10) {
        int g = tid / 10, c = tid % 10;
        float cnt = fmaxf((float)g_cnt[g], 1.f);
        float s = bfc[c];
#pragma unroll
        for (int k = 0; k < 32; k++)
            s += (g_pool[g * 32 + k] / cnt) * Wfc[k * 10 + c];
        out[tid] = s;
    }
}

// ---------------- launch ----------------
extern "C" void kernel_launch(void* const* d_in, const int* in_sizes, int n_in,
                              void* d_out, int out_size) {
    const float* x        = (const float*)d_in[0];
    const int*   ei_words = (const int*)d_in[1];
    const int*   b_words  = (const int*)d_in[2];
    const float* W1 = (const float*)d_in[3];  const float* b1 = (const float*)d_in[4];
    const float* W2 = (const float*)d_in[5];  const float* b2 = (const float*)d_in[6];
    const float* W3 = (const float*)d_in[7];  const float* b3 = (const float*)d_in[8];
    const float* W4 = (const float*)d_in[9];  const float* b4 = (const float*)d_in[10];
    const float* W5 = (const float*)d_in[11]; const float* b5 = (const float*)d_in[12];
    const float* Wfc = (const float*)d_in[13]; const float* bfc = (const float*)d_in[14];
    float* out = (float*)d_out;

    void *p_tmp, *p_A, *p_B, *p_wh;
    cudaGetSymbolAddress(&p_tmp, g_tmp);
    cudaGetSymbolAddress(&p_A, g_bufA);
    cudaGetSymbolAddress(&p_B, g_bufB);
    cudaGetSymbolAddress(&p_wh, g_wh);
    __half* tmp  = (__half*)p_tmp;
    __half* bufA = (__half*)p_A;
    __half* bufB = (__half*)p_B;
    const __half* wh = (const __half*)p_wh;

    // smem sizes
    const int SM_L1   = 2 * (128 + 128) * 40 * 2;        // 40960
    const int SMR_128 = (128 + 128) * (128 + 8) * 2;     // 69632
    const int SMR_64  = (128 + 64)  * (128 + 8) * 2;     // 52224
    const int SMR_32  = (128 + 32)  * (64 + 8)  * 2;     // 23040

    static cudaStream_t s2;
    static cudaEvent_t evFork, evJoin;
    static bool once = false;
    if (!once) {
        cudaFuncSetAttribute(h16gemm_res_kernel<128, 128>,
                             cudaFuncAttributeMaxDynamicSharedMemorySize, SMR_128);
        cudaFuncSetAttribute(h16gemm_res_kernel<64, 128>,
                             cudaFuncAttributeMaxDynamicSharedMemorySize, SMR_64);
        cudaStreamCreateWithFlags(&s2, cudaStreamNonBlocking);
        cudaEventCreateWithFlags(&evFork, cudaEventDisableTiming);
        cudaEventCreateWithFlags(&evJoin, cudaEventDisableTiming);
        once = true;
    }

    const int GEMM_GRID = (N_NODES + 127) / 128;  // 782
    const int AGG_GRID  = (N_NODES + 7) / 8;      // 12500

    // common prefix on capture stream
    detect_kernel<<<1, 256>>>(ei_words);
    init_kernel<<<391, 256>>>();
    convert_w<<<(59392 + 255) / 256, 256>>>(W1, W2, W3, W4, W5);

    // ---- fork: CSR build on s2, layer-1 GEMM on main stream (independent) ----
    cudaEventRecord(evFork, 0);
    cudaStreamWaitEvent(s2, evFork, 0);

    convert_edges<<<(N_EDGES + 255) / 256, 256, 0, s2>>>(ei_words, b_words);
    scan1_kernel<<<SCAN_NBLK, SCAN_BLK, 0, s2>>>();
    scan2_kernel<<<1, 128, 0, s2>>>();
    scan3_kernel<<<(N_NODES + 1 + 255) / 256, 256, 0, s2>>>();
    fill_kernel<<<(N_EDGES + 255) / 256, 256, 0, s2>>>(ei_words);
    cudaEventRecord(evJoin, s2);

    h16gemm_f32a_kernel<128, 128><<<GEMM_GRID, 512, SM_L1>>>(x, wh, tmp, N_NODES);

    // ---- join before aggregation (needs CSR + tmp) ----
    cudaStreamWaitEvent(0, evJoin, 0);

    // layer 1 aggregation
    agg_kernel<128><<<AGG_GRID, 256>>>(tmp, b1, bufA);
    // layer 2
    h16gemm_res_kernel<128, 128><<<GEMM_GRID, 512, SMR_128>>>(bufA, wh + 16384, tmp, N_NODES);
    agg_kernel<128><<<AGG_GRID, 256>>>(tmp, b2, bufB);
    // layer 3
    h16gemm_res_kernel<128, 128><<<GEMM_GRID, 512, SMR_128>>>(bufB, wh + 32768, tmp, N_NODES);
    agg_kernel<128><<<AGG_GRID, 256>>>(tmp, b3, bufA);
    // layer 4: 128 -> 64
    h16gemm_res_kernel<64, 128><<<GEMM_GRID, 256, SMR_64>>>(bufA, wh + 49152, tmp, N_NODES);
    agg_kernel<64><<<AGG_GRID, 256>>>(tmp, b4, bufB);
    // layer 5: 64 -> 32
    h16gemm_res_kernel<32, 64><<<GEMM_GRID, 128, SMR_32>>>(bufB, wh + 57344, tmp, N_NODES);
    agg_kernel<32><<<AGG_GRID, 256>>>(tmp, b5, bufA);

    // pool + FC
    pool_kernel<<<(N_NODES + 1023) / 1024, 256>>>(bufA);
    fc_kernel<<<1, 640>>>(Wfc, bfc, out);
}

// round 17
// speedup vs baseline: 1.0855x; 1.0054x over previous
#include <cuda_runtime.h>
#include <cuda_fp16.h>
#include <math.h>
#include <stdint.h>

#define N_NODES 100000
#define N_EDGES 1600000
#define NGRAPHS 64
#define SCAN_BLK 1024
#define SCAN_NBLK ((N_NODES + SCAN_BLK - 1) / SCAN_BLK)  // 98

// ---------------- device scratch (static globals; no allocation) ----------------
__device__ __align__(16) __half g_tmp [(size_t)N_NODES * 128];
__device__ __align__(16) __half g_bufA[(size_t)N_NODES * 128];
__device__ __align__(16) __half g_bufB[(size_t)N_NODES * 128];
// fp16 weights, transposed to [N][K]: W1@0, W2@16384, W3@32768, W4@49152, W5@57344
__device__ __align__(16) __half g_wh[59392];
__device__ int   g_batch[N_NODES];
__device__ int   g_is64;
__device__ int   g_deg[N_NODES];
__device__ float g_dinv[N_NODES];
__device__ int   g_off[N_NODES + 1];
__device__ int   g_cur[N_NODES];
__device__ __align__(8) int2 g_edge[N_EDGES];  // (src, __float_as_int(norm))
__device__ int   g_bsum[SCAN_NBLK];
__device__ float g_pool[NGRAPHS * 32];
__device__ int   g_cnt [NGRAPHS];

// ---------------- dtype detection (parallel) + conversion ----------------
__global__ void detect_kernel(const int* __restrict__ w) {
    int i = threadIdx.x;                       // 256 threads
    int v = w[2 * i + 1];
    int any = __syncthreads_or(v != 0);
    if (i == 0) g_is64 = (any == 0);
}

__global__ void init_kernel() {
    int i = blockIdx.x * blockDim.x + threadIdx.x;
    if (i < N_NODES) g_deg[i] = 1;                 // self loop
    if (i < NGRAPHS * 32) g_pool[i] = 0.f;
    if (i < NGRAPHS) g_cnt[i] = 0;
}

// fused: degree histogram (dst only) + batch convert
__global__ void convert_edges(const int* __restrict__ w, const int* __restrict__ bw) {
    int e = blockIdx.x * blockDim.x + threadIdx.x;
    if (e < N_EDGES) {
        int d = g_is64 ? w[2 * (N_EDGES + e)] : w[N_EDGES + e];
        atomicAdd(&g_deg[d], 1);
    }
    if (e < N_NODES) g_batch[e] = g_is64 ? bw[2 * e] : bw[e];
}

// Preconvert all weights to fp16, transposed [N][K]
__global__ void convert_w(const float* __restrict__ W1, const float* __restrict__ W2,
                          const float* __restrict__ W3, const float* __restrict__ W4,
                          const float* __restrict__ W5) {
    int i = blockIdx.x * blockDim.x + threadIdx.x;
    if (i < 16384) {
        int n = i >> 7, k = i & 127;
        g_wh[i] = __float2half(W1[k * 128 + n]);
    } else if (i < 32768) {
        int l = i - 16384; int n = l >> 7, k = l & 127;
        g_wh[i] = __float2half(W2[k * 128 + n]);
    } else if (i < 49152) {
        int l = i - 32768; int n = l >> 7, k = l & 127;
        g_wh[i] = __float2half(W3[k * 128 + n]);
    } else if (i < 57344) {
        int l = i - 49152; int n = l >> 7, k = l & 127;
        g_wh[i] = __float2half(W4[k * 64 + n]);
    } else if (i < 59392) {
        int l = i - 57344; int n = l >> 6, k = l & 63;
        g_wh[i] = __float2half(W5[k * 32 + n]);
    }
}

// ---------------- CSR offsets: block scan (fused dinv) ----------------
__global__ void scan1_kernel() {
    __shared__ int sw[32];
    int tid = threadIdx.x;
    int gi = blockIdx.x * SCAN_BLK + tid;
    int deg = (gi < N_NODES) ? g_deg[gi] : 1;
    if (gi < N_NODES) g_dinv[gi] = rsqrtf((float)deg);
    int val = deg - 1;
    if (gi >= N_NODES) val = 0;
    int v = val;
    int lane = tid & 31, wid = tid >> 5;
#pragma unroll
    for (int o = 1; o < 32; o <<= 1) {
        int n = __shfl_up_sync(0xffffffffu, v, o);
        if (lane >= o) v += n;
    }
    if (lane == 31) sw[wid] = v;
    __syncthreads();
    if (wid == 0) {
        int t = sw[lane];
#pragma unroll
        for (int o = 1; o < 32; o <<= 1) {
            int n = __shfl_up_sync(0xffffffffu, t, o);
            if (lane >= o) t += n;
        }
        sw[lane] = t;
    }
    __syncthreads();
    int incl = v + (wid ? sw[wid - 1] : 0);
    if (gi < N_NODES) g_off[gi] = incl - val;
    if (tid == SCAN_BLK - 1) g_bsum[blockIdx.x] = incl;
}

__global__ void scan2_kernel() {
    __shared__ int wsum[4];
    int t = threadIdx.x;
    int orig = (t < SCAN_NBLK) ? g_bsum[t] : 0;
    int v = orig;
    int lane = t & 31, wid = t >> 5;
#pragma unroll
    for (int o = 1; o < 32; o <<= 1) {
        int n = __shfl_up_sync(0xffffffffu, v, o);
        if (lane >= o) v += n;
    }
    if (lane == 31) wsum[wid] = v;
    __syncthreads();
    if (t == 0) {
        int run = 0;
#pragma unroll
        for (int i = 0; i < 4; i++) { int x = wsum[i]; wsum[i] = run; run += x; }
    }
    __syncthreads();
    if (t < SCAN_NBLK) g_bsum[t] = v - orig + wsum[wid];
}

__global__ void scan3_kernel() {
    int gi = blockIdx.x * blockDim.x + threadIdx.x;
    if (gi < N_NODES) {
        int o = g_off[gi] + g_bsum[gi >> 10];
        g_off[gi] = o;
        g_cur[gi] = o;
    }
    if (gi == N_NODES) g_off[N_NODES] = N_EDGES;
}

// reads raw edge words directly (no src/dst intermediates)
__global__ void fill_kernel(const int* __restrict__ w) {
    int e = blockIdx.x * blockDim.x + threadIdx.x;
    if (e < N_EDGES) {
        int s, d;
        if (g_is64) { s = w[2 * e]; d = w[2 * (N_EDGES + e)]; }
        else        { s = w[e];     d = w[N_EDGES + e]; }
        int pos = atomicAdd(&g_cur[d], 1);
        g_edge[pos] = make_int2(s, __float_as_int(g_dinv[s] * g_dinv[d]));
    }
}

// ---------------- shared GEMM helpers ----------------
__device__ __forceinline__ void mma_f16(float& c0, float& c1, float& c2, float& c3,
                                        uint32_t a0, uint32_t a1, uint32_t a2, uint32_t a3,
                                        uint32_t b0, uint32_t b1) {
    asm volatile(
        "mma.sync.aligned.m16n8k16.row.col.f32.f16.f16.f32 "
        "{%0,%1,%2,%3}, {%4,%5,%6,%7}, {%8,%9}, {%0,%1,%2,%3};"
        : "+f"(c0), "+f"(c1), "+f"(c2), "+f"(c3)
        : "r"(a0), "r"(a1), "r"(a2), "r"(a3), "r"(b0), "r"(b1));
}

__device__ __forceinline__ uint32_t cvta_smem(const void* p) {
    uint32_t a;
    asm("{ .reg .u64 t; cvta.to.shared.u64 t, %1; cvt.u32.u64 %0, t; }" : "=r"(a) : "l"(p));
    return a;
}

#define LDMX4(r0, r1, r2, r3, addr) \
    asm volatile("ldmatrix.sync.aligned.m8n8.x4.shared.b16 {%0,%1,%2,%3}, [%4];" \
                 : "=r"(r0), "=r"(r1), "=r"(r2), "=r"(r3) : "r"(addr))

#define CP_ASYNC16(dst, src) \
    asm volatile("cp.async.cg.shared.global [%0], [%1], 16;" :: "r"(dst), "l"(src))
#define CP_COMMIT() asm volatile("cp.async.commit_group;")
#define CP_WAIT1()  asm volatile("cp.async.wait_group 1;")
#define CP_WAIT0()  asm volatile("cp.async.wait_group 0;")

// ---------------- layer-1 GEMM: register-staged (fp32 A) ----------------
template <int BN, int K>
__global__ void __launch_bounds__(128 * (BN / 32), 2)
h16gemm_f32a_kernel(const float* __restrict__ Af, const __half* __restrict__ Wt,
                    __half* __restrict__ C, int M) {
    constexpr int BM = 128, BK = 32;
    constexpr int SK = BK + 8;
    constexpr int WARPS_N = BN / 32;
    constexpr int THREADS = 128 * WARPS_N;
    constexpr int AS1 = BM * SK;
    constexpr int BS1 = BN * SK;
    constexpr int NT = K / BK;
    constexpr int A_IT = BM * (BK / 8) / THREADS;
    constexpr int B_IT = (BN * (BK / 8) / THREADS > 0) ? BN * (BK / 8) / THREADS : 1;

    extern __shared__ __half smh[];
    __half* As = smh;
    __half* Bs = smh + 2 * AS1;

    int tid  = threadIdx.x;
    int warp = tid >> 5;
    int lane = tid & 31;
    int wm = warp / WARPS_N;
    int wn = warp % WARPS_N;
    int g = lane >> 2;
    int t = lane & 3;
    int block_row = blockIdx.x * BM;
    int l8 = lane & 7;
    int lb1 = (lane >> 3) & 1;
    int lb2 = lane >> 4;

    uint32_t As_u = cvta_smem(As);
    uint32_t Bs_u = cvta_smem(Bs);

    float acc[2][4][4];
#pragma unroll
    for (int mi = 0; mi < 2; mi++)
#pragma unroll
        for (int ni = 0; ni < 4; ni++)
#pragma unroll
            for (int r = 0; r < 4; r++) acc[mi][ni][r] = 0.f;

    uint4 ra[A_IT], rb[B_IT];

    auto load_tile = [&](int kt) {
        int k0 = kt * BK;
#pragma unroll
        for (int i = 0; i < A_IT; i++) {
            int idx = tid + i * THREADS;
            int r = idx >> 2;
            int c8 = (idx & 3) << 3;
            int gr = block_row + r;
            if (gr < M) {
                float4 f0 = *(const float4*)(Af + (size_t)gr * K + k0 + c8);
                float4 f1 = *(const float4*)(Af + (size_t)gr * K + k0 + c8 + 4);
                uint4 u;
                *(__half2*)&u.x = __floats2half2_rn(f0.x, f0.y);
                *(__half2*)&u.y = __floats2half2_rn(f0.z, f0.w);
                *(__half2*)&u.z = __floats2half2_rn(f1.x, f1.y);
                *(__half2*)&u.w = __floats2half2_rn(f1.z, f1.w);
                ra[i] = u;
            } else {
                ra[i] = make_uint4(0, 0, 0, 0);
            }
        }
#pragma unroll
        for (int i = 0; i < B_IT; i++) {
            int idx = tid + i * THREADS;
            int n = idx >> 2;
            int c8 = (idx & 3) << 3;
            rb[i] = *(const uint4*)(Wt + (size_t)n * K + k0 + c8);
        }
    };
    auto store_tile = [&](int buf) {
        __half* Ab = As + buf * AS1;
        __half* Bb = Bs + buf * BS1;
#pragma unroll
        for (int i = 0; i < A_IT; i++) {
            int idx = tid + i * THREADS;
            int r = idx >> 2;
            int c8 = (idx & 3) << 3;
            *(uint4*)(Ab + r * SK + c8) = ra[i];
        }
#pragma unroll
        for (int i = 0; i < B_IT; i++) {
            int idx = tid + i * THREADS;
            int n = idx >> 2;
            int c8 = (idx & 3) << 3;
            *(uint4*)(Bb + n * SK + c8) = rb[i];
        }
    };
    auto compute = [&](int buf) {
        uint32_t Abase = As_u + buf * (AS1 * 2);
        uint32_t Bbase = Bs_u + buf * (BS1 * 2);
#pragma unroll
        for (int kk = 0; kk < BK; kk += 16) {
            uint32_t a[2][4];
#pragma unroll
            for (int mi = 0; mi < 2; mi++) {
                uint32_t ad = Abase +
                    (uint32_t)(((wm * 32 + mi * 16 + lb1 * 8 + l8) * SK + lb2 * 8 + kk) * 2);
                LDMX4(a[mi][0], a[mi][1], a[mi][2], a[mi][3], ad);
            }
            uint32_t b[4][2];
#pragma unroll
            for (int p = 0; p < 2; p++) {
                uint32_t bd = Bbase +
                    (uint32_t)(((wn * 32 + p * 16 + lb2 * 8 + l8) * SK + lb1 * 8 + kk) * 2);
                uint32_t r0, r1, r2, r3;
                LDMX4(r0, r1, r2, r3, bd);
                b[2 * p][0] = r0; b[2 * p][1] = r1;
                b[2 * p + 1][0] = r2; b[2 * p + 1][1] = r3;
            }
#pragma unroll
            for (int mi = 0; mi < 2; mi++)
#pragma unroll
                for (int ni = 0; ni < 4; ni++)
                    mma_f16(acc[mi][ni][0], acc[mi][ni][1], acc[mi][ni][2], acc[mi][ni][3],
                            a[mi][0], a[mi][1], a[mi][2], a[mi][3],
                            b[ni][0], b[ni][1]);
        }
    };

    load_tile(0);
    store_tile(0);
    __syncthreads();
#pragma unroll
    for (int kt = 0; kt < NT; kt++) {
        if (kt + 1 < NT) load_tile(kt + 1);
        compute(kt & 1);
        if (kt + 1 < NT) {
            store_tile((kt + 1) & 1);
            __syncthreads();
        }
    }

#pragma unroll
    for (int mi = 0; mi < 2; mi++) {
        int r0 = block_row + wm * 32 + mi * 16 + g;
        int r1 = r0 + 8;
#pragma unroll
        for (int ni = 0; ni < 4; ni++) {
            int c = wn * 32 + ni * 8 + 2 * t;
            if (r0 < M)
                *(__half2*)(C + (size_t)r0 * BN + c) = __floats2half2_rn(acc[mi][ni][0], acc[mi][ni][1]);
            if (r1 < M)
                *(__half2*)(C + (size_t)r1 * BN + c) = __floats2half2_rn(acc[mi][ni][2], acc[mi][ni][3]);
        }
    }
}

// ---------------- fp16 layers: K-resident cp.async GEMM, split-K 2-group pipeline --
template <int BN, int K>
__global__ void __launch_bounds__(128 * (BN / 32), 2)
h16gemm_res_kernel(const __half* __restrict__ Ah, const __half* __restrict__ Wt,
                   __half* __restrict__ C, int M) {
    constexpr int BM = 128;
    constexpr int SK = K + 8;
    constexpr int WARPS_N = BN / 32;
    constexpr int THREADS = 128 * WARPS_N;
    constexpr int KV2 = K / 16;              // uint4 per row per K-half
    constexpr int A_OPS = BM * KV2 / THREADS;
    constexpr int B_OPS = (BN * KV2 + THREADS - 1) / THREADS;

    extern __shared__ __half smh[];
    __half* As = smh;
    __half* Bs = smh + BM * SK;

    int tid  = threadIdx.x;
    int warp = tid >> 5;
    int lane = tid & 31;
    int wm = warp / WARPS_N;
    int wn = warp % WARPS_N;
    int g = lane >> 2;
    int t = lane & 3;
    int block_row = blockIdx.x * BM;
    int l8 = lane & 7;
    int lb1 = (lane >> 3) & 1;
    int lb2 = lane >> 4;

    uint32_t As_u = cvta_smem(As);
    uint32_t Bs_u = cvta_smem(Bs);

    auto load_half = [&](int k0) {
#pragma unroll
        for (int i = 0; i < A_OPS; i++) {
            int idx = tid + i * THREADS;
            int r = idx / KV2;
            int c8 = (idx % KV2) << 3;
            int gr = block_row + r;
            if (gr >= M) gr = 0;             // clamp; masked in epilogue
            CP_ASYNC16(As_u + (uint32_t)((r * SK + k0 + c8) * 2),
                       Ah + (size_t)gr * K + k0 + c8);
        }
#pragma unroll
        for (int i = 0; i < B_OPS; i++) {
            int idx = tid + i * THREADS;
            if (BN * KV2 % THREADS == 0 || idx < BN * KV2) {
                int n = idx / KV2;
                int c8 = (idx % KV2) << 3;
                CP_ASYNC16(Bs_u + (uint32_t)((n * SK + k0 + c8) * 2),
                           Wt + (size_t)n * K + k0 + c8);
            }
        }
        CP_COMMIT();
    };

    load_half(0);
    load_half(K / 2);

    float acc[2][4][4];
#pragma unroll
    for (int mi = 0; mi < 2; mi++)
#pragma unroll
        for (int ni = 0; ni < 4; ni++)
#pragma unroll
            for (int r = 0; r < 4; r++) acc[mi][ni][r] = 0.f;

    auto compute_range = [&](int kbeg, int kend) {
#pragma unroll
        for (int kk = kbeg; kk < kend; kk += 16) {
            uint32_t a[2][4];
#pragma unroll
            for (int mi = 0; mi < 2; mi++) {
                uint32_t ad = As_u +
                    (uint32_t)(((wm * 32 + mi * 16 + lb1 * 8 + l8) * SK + lb2 * 8 + kk) * 2);
                LDMX4(a[mi][0], a[mi][1], a[mi][2], a[mi][3], ad);
            }
            uint32_t b[4][2];
#pragma unroll
            for (int p = 0; p < 2; p++) {
                uint32_t bd = Bs_u +
                    (uint32_t)(((wn * 32 + p * 16 + lb2 * 8 + l8) * SK + lb1 * 8 + kk) * 2);
                uint32_t r0, r1, r2, r3;
                LDMX4(r0, r1, r2, r3, bd);
                b[2 * p][0] = r0; b[2 * p][1] = r1;
                b[2 * p + 1][0] = r2; b[2 * p + 1][1] = r3;
            }
#pragma unroll
            for (int mi = 0; mi < 2; mi++)
#pragma unroll
                for (int ni = 0; ni < 4; ni++)
                    mma_f16(acc[mi][ni][0], acc[mi][ni][1], acc[mi][ni][2], acc[mi][ni][3],
                            a[mi][0], a[mi][1], a[mi][2], a[mi][3],
                            b[ni][0], b[ni][1]);
        }
    };

    CP_WAIT1();            // first K-half arrived
    __syncthreads();
    compute_range(0, K / 2);
    CP_WAIT0();            // second K-half arrived
    __syncthreads();
    compute_range(K / 2, K);

#pragma unroll
    for (int mi = 0; mi < 2; mi++) {
        int r0 = block_row + wm * 32 + mi * 16 + g;
        int r1 = r0 + 8;
#pragma unroll
        for (int ni = 0; ni < 4; ni++) {
            int c = wn * 32 + ni * 8 + 2 * t;
            if (r0 < M)
                *(__half2*)(C + (size_t)r0 * BN + c) = __floats2half2_rn(acc[mi][ni][0], acc[mi][ni][1]);
            if (r1 < M)
                *(__half2*)(C + (size_t)r1 * BN + c) = __floats2half2_rn(acc[mi][ni][2], acc[mi][ni][3]);
        }
    }
}

// ---------------- aggregation (warp-per-node, smem edge staging, 8-wide MLP) -------
__device__ __forceinline__ void fma_h8(float* acc, uint2 v, float w) {
    float2 f0 = __half22float2(*(const __half2*)&v.x);
    float2 f1 = __half22float2(*(const __half2*)&v.y);
    acc[0] = fmaf(w, f0.x, acc[0]); acc[1] = fmaf(w, f0.y, acc[1]);
    acc[2] = fmaf(w, f1.x, acc[2]); acc[3] = fmaf(w, f1.y, acc[3]);
}

template <int F>
__global__ void agg_kernel(const __half* __restrict__ tmp, const float* __restrict__ bias,
                           __half* __restrict__ out) {
    __shared__ int2 se[8][32];
    int wslot = threadIdx.x >> 5;
    int warp = blockIdx.x * (blockDim.x >> 5) + wslot;
    if (warp >= N_NODES) return;
    int lane = threadIdx.x & 31;
    float di = g_dinv[warp];
    float sw = di * di;
    int beg = g_off[warp], end = g_off[warp + 1];

    float acc[4];
    if constexpr (F == 128) {
        uint2 v0 = ((const uint2*)(tmp + (size_t)warp * F))[lane];
        float2 a0 = __half22float2(*(const __half2*)&v0.x);
        float2 a1 = __half22float2(*(const __half2*)&v0.y);
        acc[0] = a0.x * sw; acc[1] = a0.y * sw; acc[2] = a1.x * sw; acc[3] = a1.y * sw;
    } else if constexpr (F == 64) {
        float2 a = __half22float2(((const __half2*)(tmp + (size_t)warp * F))[lane]);
        acc[0] = a.x * sw; acc[1] = a.y * sw;
    } else {
        acc[0] = __half2float(tmp[(size_t)warp * F + lane]) * sw;
    }

    for (int e = beg; e < end; e += 32) {
        int cnt = min(32, end - e);
        __syncwarp();
        if (lane < cnt) se[wslot][lane] = g_edge[e + lane];
        __syncwarp();
        int t = 0;
        if constexpr (F == 128) {
            for (; t + 8 <= cnt; t += 8) {
                int2 q0 = se[wslot][t];     int2 q1 = se[wslot][t + 1];
                int2 q2 = se[wslot][t + 2]; int2 q3 = se[wslot][t + 3];
                int2 q4 = se[wslot][t + 4]; int2 q5 = se[wslot][t + 5];
                int2 q6 = se[wslot][t + 6]; int2 q7 = se[wslot][t + 7];
                uint2 v0 = ((const uint2*)(tmp + (size_t)q0.x * F))[lane];
                uint2 v1 = ((const uint2*)(tmp + (size_t)q1.x * F))[lane];
                uint2 v2 = ((const uint2*)(tmp + (size_t)q2.x * F))[lane];
                uint2 v3 = ((const uint2*)(tmp + (size_t)q3.x * F))[lane];
                uint2 v4 = ((const uint2*)(tmp + (size_t)q4.x * F))[lane];
                uint2 v5 = ((const uint2*)(tmp + (size_t)q5.x * F))[lane];
                uint2 v6 = ((const uint2*)(tmp + (size_t)q6.x * F))[lane];
                uint2 v7 = ((const uint2*)(tmp + (size_t)q7.x * F))[lane];
                fma_h8(acc, v0, __int_as_float(q0.y));
                fma_h8(acc, v1, __int_as_float(q1.y));
                fma_h8(acc, v2, __int_as_float(q2.y));
                fma_h8(acc, v3, __int_as_float(q3.y));
                fma_h8(acc, v4, __int_as_float(q4.y));
                fma_h8(acc, v5, __int_as_float(q5.y));
                fma_h8(acc, v6, __int_as_float(q6.y));
                fma_h8(acc, v7, __int_as_float(q7.y));
            }
            for (; t < cnt; t++) {
                int2 q = se[wslot][t];
                uint2 v = ((const uint2*)(tmp + (size_t)q.x * F))[lane];
                fma_h8(acc, v, __int_as_float(q.y));
            }
        } else if constexpr (F == 64) {
            for (; t + 8 <= cnt; t += 8) {
#pragma unroll
                for (int u = 0; u < 8; u++) {
                    int2 q = se[wslot][t + u];
                    float2 v = __half22float2(((const __half2*)(tmp + (size_t)q.x * F))[lane]);
                    float w = __int_as_float(q.y);
                    acc[0] = fmaf(w, v.x, acc[0]); acc[1] = fmaf(w, v.y, acc[1]);
                }
            }
            for (; t < cnt; t++) {
                int2 q = se[wslot][t];
                float2 v = __half22float2(((const __half2*)(tmp + (size_t)q.x * F))[lane]);
                float w = __int_as_float(q.y);
                acc[0] = fmaf(w, v.x, acc[0]); acc[1] = fmaf(w, v.y, acc[1]);
            }
        } else {
            for (; t + 8 <= cnt; t += 8) {
#pragma unroll
                for (int u = 0; u < 8; u++) {
                    int2 q = se[wslot][t + u];
                    float v = __half2float(tmp[(size_t)q.x * F + lane]);
                    acc[0] = fmaf(__int_as_float(q.y), v, acc[0]);
                }
            }
            for (; t < cnt; t++) {
                int2 q = se[wslot][t];
                float v = __half2float(tmp[(size_t)q.x * F + lane]);
                acc[0] = fmaf(__int_as_float(q.y), v, acc[0]);
            }
        }
    }

    if constexpr (F == 128) {
        float4 b = ((const float4*)bias)[lane];
        acc[0] = fmaxf(acc[0] + b.x, 0.f); acc[1] = fmaxf(acc[1] + b.y, 0.f);
        acc[2] = fmaxf(acc[2] + b.z, 0.f); acc[3] = fmaxf(acc[3] + b.w, 0.f);
        uint2 ov;
        *(__half2*)&ov.x = __floats2half2_rn(acc[0], acc[1]);
        *(__half2*)&ov.y = __floats2half2_rn(acc[2], acc[3]);
        ((uint2*)(out + (size_t)warp * F))[lane] = ov;
    } else if constexpr (F == 64) {
        float2 b = ((const float2*)bias)[lane];
        acc[0] = fmaxf(acc[0] + b.x, 0.f); acc[1] = fmaxf(acc[1] + b.y, 0.f);
        ((__half2*)(out + (size_t)warp * F))[lane] = __floats2half2_rn(acc[0], acc[1]);
    } else {
        float r = fmaxf(acc[0] + bias[lane], 0.f);
        out[(size_t)warp * F + lane] = __float2half_rn(r);
    }
}

// ---------------- global mean pool (batch is sorted) ----------------
__global__ void pool_kernel(const __half* __restrict__ h) {
    __shared__ float sp[NGRAPHS * 32];
    __shared__ int   sc[NGRAPHS];
    int tid = threadIdx.x;
    for (int i = tid; i < NGRAPHS * 32; i += 256) sp[i] = 0.f;
    for (int i = tid; i < NGRAPHS; i += 256) sc[i] = 0;
    __syncthreads();
    int wid = tid >> 5, lane = tid & 31;
    int base = blockIdx.x * 1024;
    for (int it = 0; it < 128; it++) {
        int node = base + it * 8 + wid;
        if (node < N_NODES) {
            int b = g_batch[node];
            atomicAdd(&sp[b * 32 + lane], __half2float(h[(size_t)node * 32 + lane]));
            if (lane == 0) atomicAdd(&sc[b], 1);
        }
    }
    __syncthreads();
    for (int i = tid; i < NGRAPHS * 32; i += 256) {
        float v = sp[i];
        if (v != 0.f) atomicAdd(&g_pool[i], v);
    }
    for (int i = tid; i < NGRAPHS; i += 256)
        if (sc[i]) atomicAdd(&g_cnt[i], sc[i]);
}

// ---------------- final FC ----------------
__global__ void fc_kernel(const float* __restrict__ Wfc, const float* __restrict__ bfc,
                          float* __restrict__ out) {
    int tid = threadIdx.x;
    if (tid < NGRAPHS * 10) {
        int g = tid / 10, c = tid % 10;
        float cnt = fmaxf((float)g_cnt[g], 1.f);
        float s = bfc[c];
#pragma unroll
        for (int k = 0; k < 32; k++)
            s += (g_pool[g * 32 + k] / cnt) * Wfc[k * 10 + c];
        out[tid] = s;
    }
}

// ---------------- launch ----------------
extern "C" void kernel_launch(void* const* d_in, const int* in_sizes, int n_in,
                              void* d_out, int out_size) {
    const float* x        = (const float*)d_in[0];
    const int*   ei_words = (const int*)d_in[1];
    const int*   b_words  = (const int*)d_in[2];
    const float* W1 = (const float*)d_in[3];  const float* b1 = (const float*)d_in[4];
    const float* W2 = (const float*)d_in[5];  const float* b2 = (const float*)d_in[6];
    const float* W3 = (const float*)d_in[7];  const float* b3 = (const float*)d_in[8];
    const float* W4 = (const float*)d_in[9];  const float* b4 = (const float*)d_in[10];
    const float* W5 = (const float*)d_in[11]; const float* b5 = (const float*)d_in[12];
    const float* Wfc = (const float*)d_in[13]; const float* bfc = (const float*)d_in[14];
    float* out = (float*)d_out;

    void *p_tmp, *p_A, *p_B, *p_wh;
    cudaGetSymbolAddress(&p_tmp, g_tmp);
    cudaGetSymbolAddress(&p_A, g_bufA);
    cudaGetSymbolAddress(&p_B, g_bufB);
    cudaGetSymbolAddress(&p_wh, g_wh);
    __half* tmp  = (__half*)p_tmp;
    __half* bufA = (__half*)p_A;
    __half* bufB = (__half*)p_B;
    const __half* wh = (const __half*)p_wh;

    // smem sizes
    const int SM_L1   = 2 * (128 + 128) * 40 * 2;        // 40960
    const int SMR_128 = (128 + 128) * (128 + 8) * 2;     // 69632
    const int SMR_64  = (128 + 64)  * (128 + 8) * 2;     // 52224
    const int SMR_32  = (128 + 32)  * (64 + 8)  * 2;     // 23040

    static cudaStream_t s2;
    static cudaEvent_t evFork, evJoin;
    static bool once = false;
    if (!once) {
        cudaFuncSetAttribute(h16gemm_res_kernel<128, 128>,
                             cudaFuncAttributeMaxDynamicSharedMemorySize, SMR_128);
        cudaFuncSetAttribute(h16gemm_res_kernel<64, 128>,
                             cudaFuncAttributeMaxDynamicSharedMemorySize, SMR_64);
        cudaStreamCreateWithFlags(&s2, cudaStreamNonBlocking);
        cudaEventCreateWithFlags(&evFork, cudaEventDisableTiming);
        cudaEventCreateWithFlags(&evJoin, cudaEventDisableTiming);
        once = true;
    }

    const int GEMM_GRID = (N_NODES + 127) / 128;  // 782
    const int AGG_GRID  = (N_NODES + 7) / 8;      // 12500

    // common prefix on capture stream (init MUST stay on the captured stream:
    // side-stream work is only recorded after it waits on a captured event)
    detect_kernel<<<1, 256>>>(ei_words);
    init_kernel<<<391, 256>>>();
    convert_w<<<(59392 + 255) / 256, 256>>>(W1, W2, W3, W4, W5);

    // ---- fork: CSR build on s2, layer-1 GEMM on main stream (independent) ----
    cudaEventRecord(evFork, 0);
    cudaStreamWaitEvent(s2, evFork, 0);

    convert_edges<<<(N_EDGES + 255) / 256, 256, 0, s2>>>(ei_words, b_words);
    scan1_kernel<<<SCAN_NBLK, SCAN_BLK, 0, s2>>>();
    scan2_kernel<<<1, 128, 0, s2>>>();
    scan3_kernel<<<(N_NODES + 1 + 255) / 256, 256, 0, s2>>>();
    fill_kernel<<<(N_EDGES + 255) / 256, 256, 0, s2>>>(ei_words);
    cudaEventRecord(evJoin, s2);

    h16gemm_f32a_kernel<128, 128><<<GEMM_GRID, 512, SM_L1>>>(x, wh, tmp, N_NODES);

    // ---- join before aggregation (needs CSR + tmp) ----
    cudaStreamWaitEvent(0, evJoin, 0);

    // layer 1 aggregation
    agg_kernel<128><<<AGG_GRID, 256>>>(tmp, b1, bufA);
    // layer 2
    h16gemm_res_kernel<128, 128><<<GEMM_GRID, 512, SMR_128>>>(bufA, wh + 16384, tmp, N_NODES);
    agg_kernel<128><<<AGG_GRID, 256>>>(tmp, b2, bufB);
    // layer 3
    h16gemm_res_kernel<128, 128><<<GEMM_GRID, 512, SMR_128>>>(bufB, wh + 32768, tmp, N_NODES);
    agg_kernel<128><<<AGG_GRID, 256>>>(tmp, b3, bufA);
    // layer 4: 128 -> 64
    h16gemm_res_kernel<64, 128><<<GEMM_GRID, 256, SMR_64>>>(bufA, wh + 49152, tmp, N_NODES);
    agg_kernel<64><<<AGG_GRID, 256>>>(tmp, b4, bufB);
    // layer 5: 64 -> 32
    h16gemm_res_kernel<32, 64><<<GEMM_GRID, 128, SMR_32>>>(bufB, wh + 57344, tmp, N_NODES);
    agg_kernel<32><<<AGG_GRID, 256>>>(tmp, b5, bufA);

    // pool + FC
    pool_kernel<<<(N_NODES + 1023) / 1024, 256>>>(bufA);
    fc_kernel<<<1, 640>>>(Wfc, bfc, out);
}